// round 8
// baseline (speedup 1.0000x reference)
#include <cuda_runtime.h>
#include <cstdint>

#define BATCH 4
#define LSEQ  1024
#define DMODEL 1024
#define NH    16
#define DHD   64
#define BHN   (BATCH*NH)        // 64
#define PROJ_ELEMS (BATCH*NH*LSEQ*DHD)
#define LOGIT_ELEMS ((size_t)BHN*LSEQ*LSEQ)

__device__ float g_q[PROJ_ELEMS];
__device__ float g_k[PROJ_ELEMS];
__device__ float g_v[PROJ_ELEMS];
__device__ float g_ctx[PROJ_ELEMS];
__device__ float g_logits[LOGIT_ELEMS];
__device__ float g_invs[BHN*LSEQ];

__device__ __forceinline__ uint32_t f2tf(float f) {
    uint32_t u;
    asm("cvt.rna.tf32.f32 %0, %1;" : "=r"(u) : "f"(f));
    return u;
}

__device__ __forceinline__ void mma8(float* c, const uint32_t* a, const uint32_t* b) {
    asm volatile(
        "mma.sync.aligned.m16n8k8.row.col.f32.tf32.tf32.f32 "
        "{%0,%1,%2,%3}, {%4,%5,%6,%7}, {%8,%9}, {%0,%1,%2,%3};"
        : "+f"(c[0]), "+f"(c[1]), "+f"(c[2]), "+f"(c[3])
        : "r"(a[0]), "r"(a[1]), "r"(a[2]), "r"(a[3]), "r"(b[0]), "r"(b[1]));
}

// Generic tf32 GEMM.
// BMODE 0: C = A * B^T, B stored [N][K]; BMODE 1: C = A * B, B stored [K][N]
// AMODE 1: A is [B,H,L,DH] gathered; CMODE 1: C scattered to [B,H,L,DH]
// EMODE: 0 write, 1 accumulate, 2 (acc+old)*rowscale[z*1024+r]
template<int BM, int BN, int WGM, int WGN, int AMODE, int BMODE, int CMODE, int EMODE>
__global__ void __launch_bounds__(WGM*WGN*32) gemm_tf32(
    const float* __restrict__ A, const float* __restrict__ B,
    const float* __restrict__ bias, float* __restrict__ C,
    int K,
    long long lda, long long ldb, long long ldc,
    long long sAz, long long sBz, long long sCz,
    float scale, const float* __restrict__ rowscale)
{
    constexpr int BKt = 32;
    constexpr int NT  = WGM*WGN*32;
    constexpr int WM  = BM/WGM, WN = BN/WGN;
    constexpr int MI  = WM/16,  NI = WN/8;
    constexpr int AIT = BM*8/NT;
    constexpr int BIT = (BMODE==0) ? BN*8/NT : BKt*BN/4/NT;
    constexpr int BN4 = BN/4;
    constexpr int BPAD = (BMODE==0) ? 4 : 8;

    __shared__ uint32_t sA[BM][BKt+4];
    __shared__ uint32_t sB[(BMODE==0)?BN:BKt][((BMODE==0)?BKt:BN)+BPAD];

    const int tid  = threadIdx.x;
    const int lane = tid & 31;
    const int wid  = tid >> 5;
    const int wm   = (wid % WGM) * WM;
    const int wn   = (wid / WGM) * WN;
    const int z    = blockIdx.z;
    const int bm0  = blockIdx.y * BM;
    const int bn0  = blockIdx.x * BN;

    const float* Ap = A + (long long)z * sAz;
    const float* Bp = B + (long long)z * sBz;
    float*       Cp = C + (long long)z * sCz;

    float4 f4a[AIT], f4b[BIT];

    auto loadA = [&](int kt) {
        #pragma unroll
        for (int i = 0; i < AIT; i++) {
            int idx = tid + i*NT;
            int r = idx >> 3, c = (idx & 7) << 2;
            int grow = bm0 + r;
            int gk = kt*BKt + c;
            const float* p;
            if (AMODE == 0) {
                p = Ap + (long long)grow*lda + gk;
            } else {
                int b = grow >> 10, l = grow & 1023;
                int hh = gk >> 6,  dd = gk & 63;
                p = Ap + (long long)(b*NH + hh)*(LSEQ*DHD) + l*DHD + dd;
            }
            f4a[i] = *(const float4*)p;
        }
    };
    auto loadB = [&](int kt) {
        #pragma unroll
        for (int i = 0; i < BIT; i++) {
            int idx = tid + i*NT;
            if (BMODE == 0) {
                int r = idx >> 3, c = (idx & 7) << 2;
                f4b[i] = *(const float4*)(Bp + (long long)(bn0 + r)*ldb + kt*BKt + c);
            } else {
                int r = idx / BN4, c = (idx % BN4) << 2;
                f4b[i] = *(const float4*)(Bp + (long long)(kt*BKt + r)*ldb + bn0 + c);
            }
        }
    };
    auto stsAB = [&]() {
        #pragma unroll
        for (int i = 0; i < AIT; i++) {
            int idx = tid + i*NT;
            int r = idx >> 3, c = (idx & 7) << 2;
            uint4 u = make_uint4(f2tf(f4a[i].x), f2tf(f4a[i].y), f2tf(f4a[i].z), f2tf(f4a[i].w));
            *(uint4*)&sA[r][c] = u;
        }
        #pragma unroll
        for (int i = 0; i < BIT; i++) {
            int idx = tid + i*NT;
            uint4 u = make_uint4(f2tf(f4b[i].x), f2tf(f4b[i].y), f2tf(f4b[i].z), f2tf(f4b[i].w));
            if (BMODE == 0) {
                int r = idx >> 3, c = (idx & 7) << 2;
                *(uint4*)&sB[r][c] = u;
            } else {
                int r = idx / BN4, c = (idx % BN4) << 2;
                *(uint4*)&sB[r][c] = u;
            }
        }
    };

    float acc[MI][NI][4];
    #pragma unroll
    for (int mi = 0; mi < MI; mi++)
        #pragma unroll
        for (int ni = 0; ni < NI; ni++)
            #pragma unroll
            for (int r = 0; r < 4; r++) acc[mi][ni][r] = 0.f;

    const int T = K / BKt;
    loadA(0); loadB(0);

    for (int t = 0; t < T; ++t) {
        stsAB();
        __syncthreads();
        if (t + 1 < T) { loadA(t+1); loadB(t+1); }

        #pragma unroll
        for (int kk = 0; kk < BKt; kk += 8) {
            uint32_t af[MI][4], bf[NI][2];
            #pragma unroll
            for (int mi = 0; mi < MI; mi++) {
                int r0 = wm + mi*16 + (lane >> 2);
                int c0 = kk + (lane & 3);
                af[mi][0] = sA[r0][c0];
                af[mi][1] = sA[r0 + 8][c0];
                af[mi][2] = sA[r0][c0 + 4];
                af[mi][3] = sA[r0 + 8][c0 + 4];
            }
            #pragma unroll
            for (int ni = 0; ni < NI; ni++) {
                int rn = wn + ni*8 + (lane >> 2);
                int c0 = kk + (lane & 3);
                if (BMODE == 0) {
                    bf[ni][0] = sB[rn][c0];
                    bf[ni][1] = sB[rn][c0 + 4];
                } else {
                    bf[ni][0] = sB[c0][rn];
                    bf[ni][1] = sB[c0 + 4][rn];
                }
            }
            #pragma unroll
            for (int mi = 0; mi < MI; mi++)
                #pragma unroll
                for (int ni = 0; ni < NI; ni++)
                    mma8(acc[mi][ni], af[mi], bf[ni]);
        }
        __syncthreads();
    }

    #pragma unroll
    for (int mi = 0; mi < MI; mi++) {
        #pragma unroll
        for (int ni = 0; ni < NI; ni++) {
            int mrow = bm0 + wm + mi*16 + (lane >> 2);
            int ncol = bn0 + wn + ni*8 + ((lane & 3) << 1);
            #pragma unroll
            for (int h2 = 0; h2 < 2; h2++) {
                int r = mrow + h2*8;
                float x = acc[mi][ni][h2*2 + 0];
                float y = acc[mi][ni][h2*2 + 1];
                if (bias) { x += bias[ncol]; y += bias[ncol + 1]; }
                x *= scale; y *= scale;
                long long off;
                if (CMODE == 0) {
                    off = (long long)r*ldc + ncol;
                } else {
                    int b = r >> 10, l = r & 1023;
                    int hh = ncol >> 6, dd = ncol & 63;
                    off = (long long)(b*NH + hh)*(LSEQ*DHD) + l*DHD + dd;
                }
                float2* pc = (float2*)(Cp + off);
                float2 v = make_float2(x, y);
                if (EMODE == 1) { float2 o = *pc; v.x += o.x; v.y += o.y; }
                if (EMODE == 2) {
                    float2 o = *pc;
                    float iv = rowscale[(long long)z*LSEQ + r];
                    v.x = (v.x + o.x) * iv;
                    v.y = (v.y + o.y) * iv;
                }
                *pc = v;
            }
        }
    }
}

// ---------------------------------------------------------------------------
// Pass 2 (512 threads, k-chunks of 64 -> 71KB smem -> 2 blocks/SM):
// per-q fused QR + (add QK logits) + mask + max-free softmax + AR.
// 16 warps in 4x4 grid; 16x16 tiles.
// ---------------------------------------------------------------------------
#define SQ_STRIDE 68
#define SR_STRIDE 68
#define SV_STRIDE 72
#define SAL_STRIDE 68
#define P2_SMEM_WORDS (64*SQ_STRIDE + 64*SR_STRIDE + 64*SV_STRIDE + 64*SAL_STRIDE + 64)

__global__ void __launch_bounds__(512) pass2_fused(
    const float* __restrict__ Qp,
    const float* __restrict__ relk,
    const float* __restrict__ relv,
    float* __restrict__ logits,
    const unsigned char* __restrict__ mask,
    float* __restrict__ ctx,
    float* __restrict__ invs)
{
    extern __shared__ uint32_t sm[];
    uint32_t (*sQ)[SQ_STRIDE]   = (uint32_t(*)[SQ_STRIDE])sm;
    uint32_t (*sR)[SR_STRIDE]   = (uint32_t(*)[SR_STRIDE])(sm + 64*SQ_STRIDE);
    uint32_t (*sV)[SV_STRIDE]   = (uint32_t(*)[SV_STRIDE])(sm + 64*SQ_STRIDE + 64*SR_STRIDE);
    uint32_t (*sAL)[SAL_STRIDE] = (uint32_t(*)[SAL_STRIDE])(sm + 64*SQ_STRIDE + 64*SR_STRIDE + 64*SV_STRIDE);
    float* rsum = (float*)(sm + 64*SQ_STRIDE + 64*SR_STRIDE + 64*SV_STRIDE + 64*SAL_STRIDE);

    const int q    = blockIdx.x;
    const int tid  = threadIdx.x;
    const int lane = tid & 31;
    const int wid  = tid >> 5;
    const int wm   = (wid & 3) * 16;     // row group (bh)
    const int wn   = (wid >> 2) * 16;    // col group (k local / d)

    const long long LL = (long long)LSEQ * LSEQ;

    #pragma unroll
    for (int i = 0; i < 2; i++) {
        int idx = tid + i*512;
        int r = idx >> 4, c = (idx & 15) << 2;
        float4 f = *(const float4*)(Qp + (long long)r*(LSEQ*DHD) + (long long)q*DHD + c);
        *(uint4*)&sQ[r][c] = make_uint4(f2tf(f.x), f2tf(f.y), f2tf(f.z), f2tf(f.w));
    }
    if (tid < 64) rsum[tid] = 0.f;

    const float* relkq = relk + (long long)q * (LSEQ*DHD);
    const float* relvq = relv + (long long)q * (LSEQ*DHD);

    float4 fR[2], fV[2];
    auto ldchunk = [&](int kc) {
        #pragma unroll
        for (int i = 0; i < 2; i++) {
            int idx = tid + i*512;
            int r = idx >> 4, c = (idx & 15) << 2;
            fR[i] = *(const float4*)(relkq + (long long)(kc*64 + r)*DHD + c);
            fV[i] = *(const float4*)(relvq + (long long)(kc*64 + r)*DHD + c);
        }
    };
    auto stchunk = [&]() {
        #pragma unroll
        for (int i = 0; i < 2; i++) {
            int idx = tid + i*512;
            int r = idx >> 4, c = (idx & 15) << 2;
            *(uint4*)&sR[r][c] = make_uint4(f2tf(fR[i].x), f2tf(fR[i].y), f2tf(fR[i].z), f2tf(fR[i].w));
            *(uint4*)&sV[r][c] = make_uint4(f2tf(fV[i].x), f2tf(fV[i].y), f2tf(fV[i].z), f2tf(fV[i].w));
        }
    };

    float ctxr[2][4];
    #pragma unroll
    for (int ni = 0; ni < 2; ni++)
        #pragma unroll
        for (int r = 0; r < 4; r++) ctxr[ni][r] = 0.f;
    float rs[2] = {0.f, 0.f};

    ldchunk(0);

    for (int kc = 0; kc < 16; kc++) {
        const int k0 = kc * 64;
        __syncthreads();                 // prev MMAs done reading sR/sV/sAL
        stchunk();
        __syncthreads();
        if (kc + 1 < 16) ldchunk(kc + 1);

        const int rowb = wm + (lane >> 2);
        // hoist logits + mask loads
        float2 lg[2][2];
        uchar2 mm[2][2];
        #pragma unroll
        for (int ni = 0; ni < 2; ni++) {
            int n_g = k0 + wn + ni*8 + ((lane & 3) << 1);
            #pragma unroll
            for (int h2 = 0; h2 < 2; h2++) {
                int row = rowb + h2*8;
                lg[ni][h2] = *(const float2*)(logits + (long long)row*LL + (long long)q*LSEQ + n_g);
                mm[ni][h2] = *(const uchar2*)(mask + (long long)(row >> 4)*LL + (long long)q*LSEQ + n_g);
            }
        }

        // QR MMA: S[64][64] chunk, contraction over d=64
        float S[2][4];
        #pragma unroll
        for (int ni = 0; ni < 2; ni++)
            #pragma unroll
            for (int r = 0; r < 4; r++) S[ni][r] = 0.f;

        #pragma unroll
        for (int kk = 0; kk < 64; kk += 8) {
            uint32_t af[4], bf[2][2];
            const int c0 = kk + (lane & 3);
            af[0] = sQ[rowb][c0];
            af[1] = sQ[rowb + 8][c0];
            af[2] = sQ[rowb][c0 + 4];
            af[3] = sQ[rowb + 8][c0 + 4];
            #pragma unroll
            for (int ni = 0; ni < 2; ni++) {
                int rn = wn + ni*8 + (lane >> 2);
                bf[ni][0] = sR[rn][c0];
                bf[ni][1] = sR[rn][c0 + 4];
            }
            #pragma unroll
            for (int ni = 0; ni < 2; ni++)
                mma8(S[ni], af, bf[ni]);
        }

        // combine + exp; write alpha' (global + smem)
        #pragma unroll
        for (int ni = 0; ni < 2; ni++) {
            int colL = wn + ni*8 + ((lane & 3) << 1);
            #pragma unroll
            for (int h2 = 0; h2 < 2; h2++) {
                int row = rowb + h2*8;
                float vx = S[ni][h2*2 + 0] + lg[ni][h2].x;
                float vy = S[ni][h2*2 + 1] + lg[ni][h2].y;
                if (mm[ni][h2].x) vx = -10000.f;
                if (mm[ni][h2].y) vy = -10000.f;
                float ex = __expf(vx);
                float ey = __expf(vy);
                rs[h2] += ex + ey;
                *(float2*)(logits + (long long)row*LL + (long long)q*LSEQ + k0 + colL) =
                    make_float2(ex, ey);
                sAL[row][colL]     = f2tf(ex);
                sAL[row][colL + 1] = f2tf(ey);
            }
        }
        __syncthreads();

        // AR MMA: ctxr += alpha'[64][64] * relv[q][k0:k0+64][:]
        #pragma unroll
        for (int kk = 0; kk < 64; kk += 8) {
            uint32_t af[4], bf[2][2];
            const int c0 = kk + (lane & 3);
            af[0] = sAL[rowb][c0];
            af[1] = sAL[rowb + 8][c0];
            af[2] = sAL[rowb][c0 + 4];
            af[3] = sAL[rowb + 8][c0 + 4];
            #pragma unroll
            for (int ni = 0; ni < 2; ni++) {
                int n0 = wn + ni*8 + (lane >> 2);
                bf[ni][0] = sV[c0][n0];
                bf[ni][1] = sV[c0 + 4][n0];
            }
            #pragma unroll
            for (int ni = 0; ni < 2; ni++)
                mma8(ctxr[ni], af, bf[ni]);
        }
    }

    // reduce row sums -> invs
    #pragma unroll
    for (int h2 = 0; h2 < 2; h2++) {
        float v = rs[h2];
        v += __shfl_xor_sync(0xffffffffu, v, 1);
        v += __shfl_xor_sync(0xffffffffu, v, 2);
        if ((lane & 3) == 0)
            atomicAdd(&rsum[wm + (lane >> 2) + h2*8], v);
    }
    __syncthreads();
    if (tid < 64) invs[(long long)tid*LSEQ + q] = 1.f / rsum[tid];

    // write unnormalized AR' to ctx[bh][q][d]
    #pragma unroll
    for (int ni = 0; ni < 2; ni++) {
        #pragma unroll
        for (int h2 = 0; h2 < 2; h2++) {
            int row = wm + (lane >> 2) + h2*8;
            int col = wn + ni*8 + ((lane & 3) << 1);
            *(float2*)(ctx + (long long)row*(LSEQ*DHD) + (long long)q*DHD + col) =
                make_float2(ctxr[ni][h2*2 + 0], ctxr[ni][h2*2 + 1]);
        }
    }
}

extern "C" void kernel_launch(void* const* d_in, const int* in_sizes, int n_in,
                              void* d_out, int out_size)
{
    const float* key   = (const float*)d_in[0];
    const float* value = (const float*)d_in[1];
    const float* query = (const float*)d_in[2];
    const unsigned char* mask = (const unsigned char*)d_in[3];
    const float* rel_k = (const float*)d_in[4];
    const float* rel_v = (const float*)d_in[5];
    const float* Wk = (const float*)d_in[6];
    const float* bk = (const float*)d_in[7];
    const float* Wv = (const float*)d_in[8];
    const float* bv = (const float*)d_in[9];
    const float* Wq = (const float*)d_in[10];
    const float* bq = (const float*)d_in[11];
    const float* Wo = (const float*)d_in[12];
    const float* bo = (const float*)d_in[13];
    float* out = (float*)d_out;

    float *pq, *pk, *pv, *pctx, *plog, *pinvs;
    cudaGetSymbolAddress((void**)&pq,    g_q);
    cudaGetSymbolAddress((void**)&pk,    g_k);
    cudaGetSymbolAddress((void**)&pv,    g_v);
    cudaGetSymbolAddress((void**)&pctx,  g_ctx);
    cudaGetSymbolAddress((void**)&plog,  g_logits);
    cudaGetSymbolAddress((void**)&pinvs, g_invs);

    const long long LL = (long long)LSEQ * LSEQ;
    const long long LD = (long long)LSEQ * DHD;
    const int P2_SMEM = P2_SMEM_WORDS * 4;

    static int attr_done = 0;
    if (!attr_done) {
        cudaFuncSetAttribute(pass2_fused,
            cudaFuncAttributeMaxDynamicSharedMemorySize, P2_SMEM);
        attr_done = 1;
    }

    // 1-3: QKV projections -> [B,H,L,DH]  (1024 threads, 32 warps, 50% occ)
    gemm_tf32<128,128,4,8,0,0,1,0><<<dim3(8,32,1), 1024>>>(
        key,   Wk, bk, pk, DMODEL, DMODEL, DMODEL, 0, 0, 0, 0, 1.0f, nullptr);
    gemm_tf32<128,128,4,8,0,0,1,0><<<dim3(8,32,1), 1024>>>(
        value, Wv, bv, pv, DMODEL, DMODEL, DMODEL, 0, 0, 0, 0, 1.0f, nullptr);
    gemm_tf32<128,128,4,8,0,0,1,0><<<dim3(8,32,1), 1024>>>(
        query, Wq, bq, pq, DMODEL, DMODEL, DMODEL, 0, 0, 0, 0, 0.125f, nullptr);

    // 4: QK (per batch-head): logits = Q·K^T
    gemm_tf32<128,128,4,8,0,0,0,0><<<dim3(8,8,BHN), 1024>>>(
        pq, pk, nullptr, plog, DHD,
        DHD, DHD, LSEQ,
        LD, LD, LL,
        1.0f, nullptr);

    // 5: fused QR + mask + softmax(no-max) + AR -> alpha' in plog, AR' in pctx
    pass2_fused<<<1024, 512, P2_SMEM>>>(pq, rel_k, rel_v, plog, mask, pctx, pinvs);

    // 6: AV: ctx = (alpha'·V + AR') * inv_s
    gemm_tf32<128,64,4,4,0,1,0,2><<<dim3(1,8,BHN), 512>>>(
        plog, pv, nullptr, pctx, LSEQ,
        LSEQ, DHD, DHD,
        LL, LD, LD,
        1.0f, pinvs);

    // 7: out = ctx @ Wo^T + bo
    gemm_tf32<128,128,4,8,1,0,0,0><<<dim3(8,32,1), 1024>>>(
        pctx, Wo, bo, out, DMODEL,
        0, DMODEL, DMODEL,
        0, 0, 0,
        1.0f, nullptr);
}

// round 9
// speedup vs baseline: 1.2464x; 1.2464x over previous
#include <cuda_runtime.h>
#include <cstdint>

#define BATCH 4
#define LSEQ  1024
#define DMODEL 1024
#define NH    16
#define DHD   64
#define BHN   (BATCH*NH)        // 64
#define PROJ_ELEMS (BATCH*NH*LSEQ*DHD)
#define LOGIT_ELEMS ((size_t)BHN*LSEQ*LSEQ)

__device__ float g_q[PROJ_ELEMS];
__device__ float g_k[PROJ_ELEMS];
__device__ float g_v[PROJ_ELEMS];
__device__ float g_ctx[PROJ_ELEMS];
__device__ float g_logits[LOGIT_ELEMS];
__device__ float g_invs[BHN*LSEQ];

__device__ __forceinline__ uint32_t f2tf(float f) {
    uint32_t u;
    asm("cvt.rna.tf32.f32 %0, %1;" : "=r"(u) : "f"(f));
    return u;
}

__device__ __forceinline__ void mma8(float* c, const uint32_t* a, const uint32_t* b) {
    asm volatile(
        "mma.sync.aligned.m16n8k8.row.col.f32.tf32.tf32.f32 "
        "{%0,%1,%2,%3}, {%4,%5,%6,%7}, {%8,%9}, {%0,%1,%2,%3};"
        : "+f"(c[0]), "+f"(c[1]), "+f"(c[2]), "+f"(c[3])
        : "r"(a[0]), "r"(a[1]), "r"(a[2]), "r"(a[3]), "r"(b[0]), "r"(b[1]));
}

// ldmatrix x4: loads 4 8x8 b16 matrices; for tf32 fragments the lane mapping
// (lane i -> row i>>2, 32-bit word i&3) matches mma.m16n8k8 exactly.
__device__ __forceinline__ void ldsm_x4(uint32_t* r, uint32_t a) {
    asm volatile("ldmatrix.sync.aligned.m8n8.x4.shared.b16 {%0,%1,%2,%3}, [%4];"
        : "=r"(r[0]), "=r"(r[1]), "=r"(r[2]), "=r"(r[3]) : "r"(a));
}

// Generic tf32 GEMM (r5 config base + ldmatrix fragment loads).
// BMODE 0: C = A * B^T, B stored [N][K]; BMODE 1: C = A * B, B stored [K][N]
// AMODE 1: A is [B,H,L,DH] gathered; CMODE 1: C scattered to [B,H,L,DH]
// EMODE: 0 write, 1 accumulate, 2 (acc+old)*rowscale[z*1024+r]
template<int BM, int BN, int WGM, int WGN, int AMODE, int BMODE, int CMODE, int EMODE>
__global__ void __launch_bounds__(WGM*WGN*32) gemm_tf32(
    const float* __restrict__ A, const float* __restrict__ B,
    const float* __restrict__ bias, float* __restrict__ C,
    int K,
    long long lda, long long ldb, long long ldc,
    long long sAz, long long sBz, long long sCz,
    float scale, const float* __restrict__ rowscale)
{
    constexpr int BKt = 32;
    constexpr int NT  = WGM*WGN*32;
    constexpr int WM  = BM/WGM, WN = BN/WGN;
    constexpr int MI  = WM/16,  NI = WN/8;
    constexpr int AIT = BM*8/NT;
    constexpr int BIT = (BMODE==0) ? BN*8/NT : BKt*BN/4/NT;
    constexpr int BN4 = BN/4;
    constexpr int BPAD = (BMODE==0) ? 4 : 8;

    __shared__ uint32_t sA[BM][BKt+4];
    __shared__ uint32_t sB[(BMODE==0)?BN:BKt][((BMODE==0)?BKt:BN)+BPAD];

    const int tid  = threadIdx.x;
    const int lane = tid & 31;
    const int wid  = tid >> 5;
    const int wm   = (wid % WGM) * WM;
    const int wn   = (wid / WGM) * WN;
    const int z    = blockIdx.z;
    const int bm0  = blockIdx.y * BM;
    const int bn0  = blockIdx.x * BN;

    const float* Ap = A + (long long)z * sAz;
    const float* Bp = B + (long long)z * sBz;
    float*       Cp = C + (long long)z * sCz;

    const uint32_t sA_base = (uint32_t)__cvta_generic_to_shared(&sA[0][0]);
    const uint32_t sB_base = (uint32_t)__cvta_generic_to_shared(&sB[0][0]);
    // ldmatrix per-lane source row/col offsets
    const int a_row_l = (lane & 7) + ((lane >> 3) & 1) * 8;
    const int a_col_l = (lane >> 4) * 4;
    const int b_row_l = (lane & 7) + ((lane >> 4) & 1) * 8;
    const int b_col_l = ((lane >> 3) & 1) * 4;

    float4 f4a[AIT], f4b[BIT];

    auto loadA = [&](int kt) {
        #pragma unroll
        for (int i = 0; i < AIT; i++) {
            int idx = tid + i*NT;
            int r = idx >> 3, c = (idx & 7) << 2;
            int grow = bm0 + r;
            int gk = kt*BKt + c;
            const float* p;
            if (AMODE == 0) {
                p = Ap + (long long)grow*lda + gk;
            } else {
                int b = grow >> 10, l = grow & 1023;
                int hh = gk >> 6,  dd = gk & 63;
                p = Ap + (long long)(b*NH + hh)*(LSEQ*DHD) + l*DHD + dd;
            }
            f4a[i] = *(const float4*)p;
        }
    };
    auto loadB = [&](int kt) {
        #pragma unroll
        for (int i = 0; i < BIT; i++) {
            int idx = tid + i*NT;
            if (BMODE == 0) {
                int r = idx >> 3, c = (idx & 7) << 2;
                f4b[i] = *(const float4*)(Bp + (long long)(bn0 + r)*ldb + kt*BKt + c);
            } else {
                int r = idx / BN4, c = (idx % BN4) << 2;
                f4b[i] = *(const float4*)(Bp + (long long)(kt*BKt + r)*ldb + bn0 + c);
            }
        }
    };
    auto stsAB = [&]() {
        #pragma unroll
        for (int i = 0; i < AIT; i++) {
            int idx = tid + i*NT;
            int r = idx >> 3, c = (idx & 7) << 2;
            uint4 u = make_uint4(f2tf(f4a[i].x), f2tf(f4a[i].y), f2tf(f4a[i].z), f2tf(f4a[i].w));
            *(uint4*)&sA[r][c] = u;
        }
        #pragma unroll
        for (int i = 0; i < BIT; i++) {
            int idx = tid + i*NT;
            uint4 u = make_uint4(f2tf(f4b[i].x), f2tf(f4b[i].y), f2tf(f4b[i].z), f2tf(f4b[i].w));
            if (BMODE == 0) {
                int r = idx >> 3, c = (idx & 7) << 2;
                *(uint4*)&sB[r][c] = u;
            } else {
                int r = idx / BN4, c = (idx % BN4) << 2;
                *(uint4*)&sB[r][c] = u;
            }
        }
    };

    float acc[MI][NI][4];
    #pragma unroll
    for (int mi = 0; mi < MI; mi++)
        #pragma unroll
        for (int ni = 0; ni < NI; ni++)
            #pragma unroll
            for (int r = 0; r < 4; r++) acc[mi][ni][r] = 0.f;

    const int T = K / BKt;
    loadA(0); loadB(0);

    for (int t = 0; t < T; ++t) {
        stsAB();
        __syncthreads();
        if (t + 1 < T) { loadA(t+1); loadB(t+1); }

        #pragma unroll
        for (int kk = 0; kk < BKt; kk += 8) {
            uint32_t af[MI][4], bf[NI][2];
            #pragma unroll
            for (int mi = 0; mi < MI; mi++)
                ldsm_x4(af[mi],
                    sA_base + (((wm + mi*16 + a_row_l)*(BKt+4) + kk + a_col_l) << 2));
            if (BMODE == 0 && (NI & 1) == 0) {
                #pragma unroll
                for (int np = 0; np < NI; np += 2)
                    ldsm_x4(&bf[np][0],
                        sB_base + (((wn + np*8 + b_row_l)*(BKt+4) + kk + b_col_l) << 2));
            } else {
                #pragma unroll
                for (int ni = 0; ni < NI; ni++) {
                    int rn = wn + ni*8 + (lane >> 2);
                    int c0 = kk + (lane & 3);
                    if (BMODE == 0) {
                        bf[ni][0] = sB[rn][c0];
                        bf[ni][1] = sB[rn][c0 + 4];
                    } else {
                        bf[ni][0] = sB[c0][rn];
                        bf[ni][1] = sB[c0 + 4][rn];
                    }
                }
            }
            #pragma unroll
            for (int mi = 0; mi < MI; mi++)
                #pragma unroll
                for (int ni = 0; ni < NI; ni++)
                    mma8(acc[mi][ni], af[mi], bf[ni]);
        }
        __syncthreads();
    }

    #pragma unroll
    for (int mi = 0; mi < MI; mi++) {
        #pragma unroll
        for (int ni = 0; ni < NI; ni++) {
            int mrow = bm0 + wm + mi*16 + (lane >> 2);
            int ncol = bn0 + wn + ni*8 + ((lane & 3) << 1);
            #pragma unroll
            for (int h2 = 0; h2 < 2; h2++) {
                int r = mrow + h2*8;
                float x = acc[mi][ni][h2*2 + 0];
                float y = acc[mi][ni][h2*2 + 1];
                if (bias) { x += bias[ncol]; y += bias[ncol + 1]; }
                x *= scale; y *= scale;
                long long off;
                if (CMODE == 0) {
                    off = (long long)r*ldc + ncol;
                } else {
                    int b = r >> 10, l = r & 1023;
                    int hh = ncol >> 6, dd = ncol & 63;
                    off = (long long)(b*NH + hh)*(LSEQ*DHD) + l*DHD + dd;
                }
                float2* pc = (float2*)(Cp + off);
                float2 v = make_float2(x, y);
                if (EMODE == 1) { float2 o = *pc; v.x += o.x; v.y += o.y; }
                if (EMODE == 2) {
                    float2 o = *pc;
                    float iv = rowscale[(long long)z*LSEQ + r];
                    v.x = (v.x + o.x) * iv;
                    v.y = (v.y + o.y) * iv;
                }
                *pc = v;
            }
        }
    }
}

// ---------------------------------------------------------------------------
// Pass 2 (512 threads, r5 layout: k-chunks of 128, register prefetch,
// ldmatrix fragment loads). Block = one q row; M = 64 batch-heads.
// 16 warps in 4(row)x4(col); QR tiles 16x32, AR tiles 16x16.
// ---------------------------------------------------------------------------
#define SQ_STRIDE 68
#define SR_STRIDE 68
#define SV_STRIDE 72
#define SAL_STRIDE 132
#define P2_SMEM_WORDS (64*SQ_STRIDE + 128*SR_STRIDE + 128*SV_STRIDE + 64*SAL_STRIDE + 64)

__global__ void __launch_bounds__(512) pass2_fused(
    const float* __restrict__ Qp,
    const float* __restrict__ relk,
    const float* __restrict__ relv,
    float* __restrict__ logits,
    const unsigned char* __restrict__ mask,
    float* __restrict__ ctx,
    float* __restrict__ invs)
{
    extern __shared__ uint32_t sm[];
    uint32_t (*sQ)[SQ_STRIDE]   = (uint32_t(*)[SQ_STRIDE])sm;
    uint32_t (*sR)[SR_STRIDE]   = (uint32_t(*)[SR_STRIDE])(sm + 64*SQ_STRIDE);
    uint32_t (*sV)[SV_STRIDE]   = (uint32_t(*)[SV_STRIDE])(sm + 64*SQ_STRIDE + 128*SR_STRIDE);
    uint32_t (*sAL)[SAL_STRIDE] = (uint32_t(*)[SAL_STRIDE])(sm + 64*SQ_STRIDE + 128*SR_STRIDE + 128*SV_STRIDE);
    float* rsum = (float*)(sm + 64*SQ_STRIDE + 128*SR_STRIDE + 128*SV_STRIDE + 64*SAL_STRIDE);

    const int q    = blockIdx.x;
    const int tid  = threadIdx.x;
    const int lane = tid & 31;
    const int wid  = tid >> 5;
    const int wm   = (wid & 3) * 16;          // row group (bh)
    const int wn   = (wid >> 2) * 32;         // QR col group
    const int wnA  = (wid >> 2) * 16;         // AR col group

    const long long LL = (long long)LSEQ * LSEQ;

    const uint32_t sQ_base  = (uint32_t)__cvta_generic_to_shared(&sQ[0][0]);
    const uint32_t sR_base  = (uint32_t)__cvta_generic_to_shared(&sR[0][0]);
    const uint32_t sAL_base = (uint32_t)__cvta_generic_to_shared(&sAL[0][0]);
    const int a_row_l = (lane & 7) + ((lane >> 3) & 1) * 8;
    const int a_col_l = (lane >> 4) * 4;
    const int b_row_l = (lane & 7) + ((lane >> 4) & 1) * 8;
    const int b_col_l = ((lane >> 3) & 1) * 4;

    #pragma unroll
    for (int i = 0; i < 2; i++) {
        int idx = tid + i*512;
        int r = idx >> 4, c = (idx & 15) << 2;
        float4 f = *(const float4*)(Qp + (long long)r*(LSEQ*DHD) + (long long)q*DHD + c);
        *(uint4*)&sQ[r][c] = make_uint4(f2tf(f.x), f2tf(f.y), f2tf(f.z), f2tf(f.w));
    }
    if (tid < 64) rsum[tid] = 0.f;

    const float* relkq = relk + (long long)q * (LSEQ*DHD);
    const float* relvq = relv + (long long)q * (LSEQ*DHD);

    float4 fR[4], fV[4];
    auto ldchunk = [&](int kc) {
        #pragma unroll
        for (int i = 0; i < 4; i++) {
            int idx = tid + i*512;
            int r = idx >> 4, c = (idx & 15) << 2;
            fR[i] = *(const float4*)(relkq + (long long)(kc*128 + r)*DHD + c);
            fV[i] = *(const float4*)(relvq + (long long)(kc*128 + r)*DHD + c);
        }
    };
    auto stchunk = [&]() {
        #pragma unroll
        for (int i = 0; i < 4; i++) {
            int idx = tid + i*512;
            int r = idx >> 4, c = (idx & 15) << 2;
            *(uint4*)&sR[r][c] = make_uint4(f2tf(fR[i].x), f2tf(fR[i].y), f2tf(fR[i].z), f2tf(fR[i].w));
            *(uint4*)&sV[r][c] = make_uint4(f2tf(fV[i].x), f2tf(fV[i].y), f2tf(fV[i].z), f2tf(fV[i].w));
        }
    };

    float ctxr[2][4];
    #pragma unroll
    for (int ni = 0; ni < 2; ni++)
        #pragma unroll
        for (int r = 0; r < 4; r++) ctxr[ni][r] = 0.f;
    float rs[2] = {0.f, 0.f};

    ldchunk(0);

    for (int kc = 0; kc < 8; kc++) {
        const int k0 = kc * 128;
        __syncthreads();                  // prev MMAs done reading sR/sV/sAL
        stchunk();
        __syncthreads();
        if (kc + 1 < 8) ldchunk(kc + 1);  // prefetch next chunk

        const int rowb = wm + (lane >> 2);
        // hoist logits + mask loads (overlap with QR MMA)
        float2 lg[4][2];
        uchar2 mm[4][2];
        #pragma unroll
        for (int ni = 0; ni < 4; ni++) {
            int n_g = k0 + wn + ni*8 + ((lane & 3) << 1);
            #pragma unroll
            for (int h2 = 0; h2 < 2; h2++) {
                int row = rowb + h2*8;
                lg[ni][h2] = *(const float2*)(logits + (long long)row*LL + (long long)q*LSEQ + n_g);
                mm[ni][h2] = *(const uchar2*)(mask + (long long)(row >> 4)*LL + (long long)q*LSEQ + n_g);
            }
        }

        // QR MMA: S[64][128] chunk (contraction d=64), ldmatrix feeds
        float S[4][4];
        #pragma unroll
        for (int ni = 0; ni < 4; ni++)
            #pragma unroll
            for (int r = 0; r < 4; r++) S[ni][r] = 0.f;

        #pragma unroll
        for (int kk = 0; kk < 64; kk += 8) {
            uint32_t af[4], bf[4][2];
            ldsm_x4(af, sQ_base + (((wm + a_row_l)*SQ_STRIDE + kk + a_col_l) << 2));
            #pragma unroll
            for (int np = 0; np < 4; np += 2)
                ldsm_x4(&bf[np][0],
                    sR_base + (((wn + np*8 + b_row_l)*SR_STRIDE + kk + b_col_l) << 2));
            #pragma unroll
            for (int ni = 0; ni < 4; ni++)
                mma8(S[ni], af, bf[ni]);
        }

        // combine + exp; write alpha' (global + smem)
        #pragma unroll
        for (int ni = 0; ni < 4; ni++) {
            int colL = wn + ni*8 + ((lane & 3) << 1);
            #pragma unroll
            for (int h2 = 0; h2 < 2; h2++) {
                int row = rowb + h2*8;
                float vx = S[ni][h2*2 + 0] + lg[ni][h2].x;
                float vy = S[ni][h2*2 + 1] + lg[ni][h2].y;
                if (mm[ni][h2].x) vx = -10000.f;
                if (mm[ni][h2].y) vy = -10000.f;
                float ex = __expf(vx);
                float ey = __expf(vy);
                rs[h2] += ex + ey;
                *(float2*)(logits + (long long)row*LL + (long long)q*LSEQ + k0 + colL) =
                    make_float2(ex, ey);
                sAL[row][colL]     = f2tf(ex);
                sAL[row][colL + 1] = f2tf(ey);
            }
        }
        __syncthreads();

        // AR MMA: ctxr += alpha'[64][128] * relv[q][k0:k0+128][:]
        #pragma unroll
        for (int kk = 0; kk < 128; kk += 8) {
            uint32_t af[4], bf[2][2];
            ldsm_x4(af, sAL_base + (((wm + a_row_l)*SAL_STRIDE + kk + a_col_l) << 2));
            const int c0 = kk + (lane & 3);
            #pragma unroll
            for (int ni = 0; ni < 2; ni++) {
                int n0 = wnA + ni*8 + (lane >> 2);
                bf[ni][0] = sV[c0][n0];
                bf[ni][1] = sV[c0 + 4][n0];
            }
            #pragma unroll
            for (int ni = 0; ni < 2; ni++)
                mma8(ctxr[ni], af, bf[ni]);
        }
    }

    // reduce row sums -> invs
    #pragma unroll
    for (int h2 = 0; h2 < 2; h2++) {
        float v = rs[h2];
        v += __shfl_xor_sync(0xffffffffu, v, 1);
        v += __shfl_xor_sync(0xffffffffu, v, 2);
        if ((lane & 3) == 0)
            atomicAdd(&rsum[wm + (lane >> 2) + h2*8], v);
    }
    __syncthreads();
    if (tid < 64) invs[(long long)tid*LSEQ + q] = 1.f / rsum[tid];

    // write unnormalized AR' to ctx[bh][q][d]
    #pragma unroll
    for (int ni = 0; ni < 2; ni++) {
        #pragma unroll
        for (int h2 = 0; h2 < 2; h2++) {
            int row = wm + (lane >> 2) + h2*8;
            int col = wnA + ni*8 + ((lane & 3) << 1);
            *(float2*)(ctx + (long long)row*(LSEQ*DHD) + (long long)q*DHD + col) =
                make_float2(ctxr[ni][h2*2 + 0], ctxr[ni][h2*2 + 1]);
        }
    }
}

extern "C" void kernel_launch(void* const* d_in, const int* in_sizes, int n_in,
                              void* d_out, int out_size)
{
    const float* key   = (const float*)d_in[0];
    const float* value = (const float*)d_in[1];
    const float* query = (const float*)d_in[2];
    const unsigned char* mask = (const unsigned char*)d_in[3];
    const float* rel_k = (const float*)d_in[4];
    const float* rel_v = (const float*)d_in[5];
    const float* Wk = (const float*)d_in[6];
    const float* bk = (const float*)d_in[7];
    const float* Wv = (const float*)d_in[8];
    const float* bv = (const float*)d_in[9];
    const float* Wq = (const float*)d_in[10];
    const float* bq = (const float*)d_in[11];
    const float* Wo = (const float*)d_in[12];
    const float* bo = (const float*)d_in[13];
    float* out = (float*)d_out;

    float *pq, *pk, *pv, *pctx, *plog, *pinvs;
    cudaGetSymbolAddress((void**)&pq,    g_q);
    cudaGetSymbolAddress((void**)&pk,    g_k);
    cudaGetSymbolAddress((void**)&pv,    g_v);
    cudaGetSymbolAddress((void**)&pctx,  g_ctx);
    cudaGetSymbolAddress((void**)&plog,  g_logits);
    cudaGetSymbolAddress((void**)&pinvs, g_invs);

    const long long LL = (long long)LSEQ * LSEQ;
    const long long LD = (long long)LSEQ * DHD;
    const int P2_SMEM = P2_SMEM_WORDS * 4;

    static int attr_done = 0;
    if (!attr_done) {
        cudaFuncSetAttribute(pass2_fused,
            cudaFuncAttributeMaxDynamicSharedMemorySize, P2_SMEM);
        attr_done = 1;
    }

    // 1-3: QKV projections -> [B,H,L,DH]  (r5 config: 512 threads, 16 warps)
    gemm_tf32<128,128,4,4,0,0,1,0><<<dim3(8,32,1), 512>>>(
        key,   Wk, bk, pk, DMODEL, DMODEL, DMODEL, 0, 0, 0, 0, 1.0f, nullptr);
    gemm_tf32<128,128,4,4,0,0,1,0><<<dim3(8,32,1), 512>>>(
        value, Wv, bv, pv, DMODEL, DMODEL, DMODEL, 0, 0, 0, 0, 1.0f, nullptr);
    gemm_tf32<128,128,4,4,0,0,1,0><<<dim3(8,32,1), 512>>>(
        query, Wq, bq, pq, DMODEL, DMODEL, DMODEL, 0, 0, 0, 0, 0.125f, nullptr);

    // 4: QK (per batch-head): logits = Q·K^T
    gemm_tf32<128,128,4,4,0,0,0,0><<<dim3(8,8,BHN), 512>>>(
        pq, pk, nullptr, plog, DHD,
        DHD, DHD, LSEQ,
        LD, LD, LL,
        1.0f, nullptr);

    // 5: fused QR + mask + softmax(no-max) + AR -> alpha' in plog, AR' in pctx
    pass2_fused<<<1024, 512, P2_SMEM>>>(pq, rel_k, rel_v, plog, mask, pctx, pinvs);

    // 6: AV: ctx = (alpha'·V + AR') * inv_s
    gemm_tf32<128,64,8,2,0,1,0,2><<<dim3(1,8,BHN), 512>>>(
        plog, pv, nullptr, pctx, LSEQ,
        LSEQ, DHD, DHD,
        LL, LD, LD,
        1.0f, pinvs);

    // 7: out = ctx @ Wo^T + bo
    gemm_tf32<128,128,4,4,1,0,0,0><<<dim3(8,32,1), 512>>>(
        pctx, Wo, bo, out, DMODEL,
        0, DMODEL, DMODEL,
        0, 0, 0,
        1.0f, nullptr);
}

// round 10
// speedup vs baseline: 1.8762x; 1.5053x over previous
#include <cuda_runtime.h>
#include <cuda_fp16.h>
#include <cstdint>

#define BATCH 4
#define LSEQ  1024
#define DMODEL 1024
#define NH    16
#define DHD   64
#define BHN   (BATCH*NH)        // 64
#define PROJ_ELEMS (BATCH*NH*LSEQ*DHD)
#define LOGIT_ELEMS ((size_t)BHN*LSEQ*LSEQ)

// fp16 intermediates (halved DRAM traffic vs fp32)
__device__ __half g_q[PROJ_ELEMS];
__device__ __half g_k[PROJ_ELEMS];
__device__ __half g_v[PROJ_ELEMS];
__device__ __half g_ctx[PROJ_ELEMS];
__device__ __half g_logits[LOGIT_ELEMS];
__device__ float  g_invs[BHN*LSEQ];

__device__ __forceinline__ uint32_t h2pack(float x, float y) {
    __half2 h = __floats2half2_rn(x, y);
    return *(uint32_t*)&h;
}

__device__ __forceinline__ void mma16(float* c, const uint32_t* a, const uint32_t* b) {
    asm volatile(
        "mma.sync.aligned.m16n8k16.row.col.f32.f16.f16.f32 "
        "{%0,%1,%2,%3}, {%4,%5,%6,%7}, {%8,%9}, {%0,%1,%2,%3};"
        : "+f"(c[0]), "+f"(c[1]), "+f"(c[2]), "+f"(c[3])
        : "r"(a[0]), "r"(a[1]), "r"(a[2]), "r"(a[3]), "r"(b[0]), "r"(b[1]));
}

__device__ __forceinline__ void ldsm_x4(uint32_t* r, uint32_t a) {
    asm volatile("ldmatrix.sync.aligned.m8n8.x4.shared.b16 {%0,%1,%2,%3}, [%4];"
        : "=r"(r[0]), "=r"(r[1]), "=r"(r[2]), "=r"(r[3]) : "r"(a));
}
__device__ __forceinline__ void ldsm_x4_t(uint32_t* r, uint32_t a) {
    asm volatile("ldmatrix.sync.aligned.m8n8.x4.trans.shared.b16 {%0,%1,%2,%3}, [%4];"
        : "=r"(r[0]), "=r"(r[1]), "=r"(r[2]), "=r"(r[3]) : "r"(a));
}

// ---------------------------------------------------------------------------
// Generic fp16-input / fp32-accumulate GEMM.
// BMODE 0: C = A * B^T, B stored [N][K]; BMODE 1: C = A * B, B stored [K][N]
// AMODE 1: A is [B,H,L,DH] gathered (r=(b,l), k=(h,dh))
// CMODE 1: C scattered to [B,H,L,DH]
// EMODE 0: write; EMODE 2: v = (acc + old) * rowscale[z*1024+r]
// TA/TB in {float,__half} (converted to fp16 at load); TC in {float,__half}.
// K must be a multiple of 64.
// ---------------------------------------------------------------------------
template<class TA, class TB, class TC, int BM, int BN, int WGM, int WGN,
         int AMODE, int BMODE, int CMODE, int EMODE>
__global__ void __launch_bounds__(WGM*WGN*32) gemm_h(
    const TA* __restrict__ A, const TB* __restrict__ B,
    const float* __restrict__ bias, TC* __restrict__ C,
    int K,
    long long lda, long long ldb, long long ldc,
    long long sAz, long long sBz, long long sCz,
    float scale, const float* __restrict__ rowscale)
{
    constexpr int BK  = 64;                 // halves per k-tile
    constexpr int NT  = WGM*WGN*32;
    constexpr int WM  = BM/WGM, WN = BN/WGN;
    constexpr int MI  = WM/16,  NI = WN/8;
    constexpr int AIT = BM*8/NT;            // uint4 (8-half) chunks per thread
    constexpr int BIT = (BMODE==0) ? BN*8/NT : BK*(BN/8)/NT;
    constexpr int LDA = BK + 8;             // half stride, 16B pad
    constexpr int LDB = ((BMODE==0)?BK:BN) + 8;
    constexpr int BROWS = (BMODE==0)?BN:BK;

    __shared__ __half sA[BM][LDA];
    __shared__ __half sB[BROWS][LDB];

    const int tid  = threadIdx.x;
    const int lane = tid & 31;
    const int wid  = tid >> 5;
    const int wm   = (wid % WGM) * WM;
    const int wn   = (wid / WGM) * WN;
    const int z    = blockIdx.z;
    const int bm0  = blockIdx.y * BM;
    const int bn0  = blockIdx.x * BN;

    const TA* Ap = A + (long long)z * sAz;
    const TB* Bp = B + (long long)z * sBz;
    TC*       Cp = C + (long long)z * sCz;

    const uint32_t sA_base = (uint32_t)__cvta_generic_to_shared(&sA[0][0]);
    const uint32_t sB_base = (uint32_t)__cvta_generic_to_shared(&sB[0][0]);
    // ldmatrix per-lane offsets
    const int a_row = (lane & 7) + ((lane >> 3) & 1) * 8;
    const int a_k8  = ((lane >> 4) & 1) * 8;
    const int b_row = (lane & 7) + ((lane >> 4) & 1) * 8;
    const int b_k8  = ((lane >> 3) & 1) * 8;
    const int t_k   = (lane & 7) + ((lane >> 3) & 1) * 8;   // trans: k offset
    const int t_n8  = ((lane >> 4) & 1) * 8;                // trans: n offset

    uint4 rga[AIT], rgb[BIT];

    auto loadA = [&](int kt) {
        #pragma unroll
        for (int i = 0; i < AIT; i++) {
            int idx = tid + i*NT;
            int r = idx >> 3, c = (idx & 7) << 3;
            int grow = bm0 + r;
            int gk = kt*BK + c;
            const TA* p;
            if (AMODE == 0) {
                p = Ap + (long long)grow*lda + gk;
            } else {
                int b = grow >> 10, l = grow & 1023;
                int hh = gk >> 6,  dd = gk & 63;
                p = Ap + (long long)(b*NH + hh)*(LSEQ*DHD) + l*DHD + dd;
            }
            if constexpr (sizeof(TA) == 4) {
                float4 u0 = *(const float4*)p;
                float4 u1 = *(const float4*)(p + 4);
                rga[i] = make_uint4(h2pack(u0.x,u0.y), h2pack(u0.z,u0.w),
                                    h2pack(u1.x,u1.y), h2pack(u1.z,u1.w));
            } else {
                rga[i] = *(const uint4*)p;
            }
        }
    };
    auto loadB = [&](int kt) {
        #pragma unroll
        for (int i = 0; i < BIT; i++) {
            int idx = tid + i*NT;
            const TB* p;
            if (BMODE == 0) {
                int r = idx >> 3, c = (idx & 7) << 3;
                p = Bp + (long long)(bn0 + r)*ldb + kt*BK + c;
            } else {
                int r = idx / (BN/8), c = (idx % (BN/8)) << 3;
                p = Bp + (long long)(kt*BK + r)*ldb + bn0 + c;
            }
            if constexpr (sizeof(TB) == 4) {
                float4 u0 = *(const float4*)p;
                float4 u1 = *(const float4*)(p + 4);
                rgb[i] = make_uint4(h2pack(u0.x,u0.y), h2pack(u0.z,u0.w),
                                    h2pack(u1.x,u1.y), h2pack(u1.z,u1.w));
            } else {
                rgb[i] = *(const uint4*)p;
            }
        }
    };
    auto stsAB = [&]() {
        #pragma unroll
        for (int i = 0; i < AIT; i++) {
            int idx = tid + i*NT;
            int r = idx >> 3, c = (idx & 7) << 3;
            *(uint4*)&sA[r][c] = rga[i];
        }
        #pragma unroll
        for (int i = 0; i < BIT; i++) {
            int idx = tid + i*NT;
            if (BMODE == 0) {
                int r = idx >> 3, c = (idx & 7) << 3;
                *(uint4*)&sB[r][c] = rgb[i];
            } else {
                int r = idx / (BN/8), c = (idx % (BN/8)) << 3;
                *(uint4*)&sB[r][c] = rgb[i];
            }
        }
    };

    float acc[MI][NI][4];
    #pragma unroll
    for (int mi = 0; mi < MI; mi++)
        #pragma unroll
        for (int ni = 0; ni < NI; ni++)
            #pragma unroll
            for (int r = 0; r < 4; r++) acc[mi][ni][r] = 0.f;

    const int T = K / BK;
    loadA(0); loadB(0);

    for (int t = 0; t < T; ++t) {
        stsAB();
        __syncthreads();
        if (t + 1 < T) { loadA(t+1); loadB(t+1); }

        #pragma unroll
        for (int kk = 0; kk < BK; kk += 16) {
            uint32_t af[MI][4], bf[NI][2];
            #pragma unroll
            for (int mi = 0; mi < MI; mi++)
                ldsm_x4(af[mi],
                    sA_base + (((wm + mi*16 + a_row)*LDA + kk + a_k8) << 1));
            #pragma unroll
            for (int np = 0; np < NI; np += 2) {
                if (BMODE == 0)
                    ldsm_x4(&bf[np][0],
                        sB_base + (((wn + np*8 + b_row)*LDB + kk + b_k8) << 1));
                else
                    ldsm_x4_t(&bf[np][0],
                        sB_base + (((kk + t_k)*LDB + wn + np*8 + t_n8) << 1));
            }
            #pragma unroll
            for (int mi = 0; mi < MI; mi++)
                #pragma unroll
                for (int ni = 0; ni < NI; ni++)
                    mma16(acc[mi][ni], af[mi], bf[ni]);
        }
        __syncthreads();
    }

    #pragma unroll
    for (int mi = 0; mi < MI; mi++) {
        #pragma unroll
        for (int ni = 0; ni < NI; ni++) {
            int mrow = bm0 + wm + mi*16 + (lane >> 2);
            int ncol = bn0 + wn + ni*8 + ((lane & 3) << 1);
            #pragma unroll
            for (int h2 = 0; h2 < 2; h2++) {
                int r = mrow + h2*8;
                float x = acc[mi][ni][h2*2 + 0];
                float y = acc[mi][ni][h2*2 + 1];
                if (bias) { x += bias[ncol]; y += bias[ncol + 1]; }
                x *= scale; y *= scale;
                long long off;
                if (CMODE == 0) {
                    off = (long long)r*ldc + ncol;
                } else {
                    int b = r >> 10, l = r & 1023;
                    int hh = ncol >> 6, dd = ncol & 63;
                    off = (long long)(b*NH + hh)*(LSEQ*DHD) + l*DHD + dd;
                }
                if (EMODE == 2) {
                    float2 o = __half22float2(*(const __half2*)(Cp + off));
                    float iv = rowscale[(long long)z*LSEQ + r];
                    x = (x + o.x) * iv;
                    y = (y + o.y) * iv;
                }
                if constexpr (sizeof(TC) == 4) {
                    *(float2*)(Cp + off) = make_float2(x, y);
                } else {
                    *(__half2*)(Cp + off) = __floats2half2_rn(x, y);
                }
            }
        }
    }
}

// ---------------------------------------------------------------------------
// Pass 2 (512 threads, fp16): per-q fused QR + (add QK logits) + mask +
// max-free softmax + AR, register prefetch of next rel chunk.
// Block = one q row; M = 64 batch-heads, keys in chunks of 128.
// 16 warps 4(row)x4(col): QR tiles 16x32, AR tiles 16x16.
// ---------------------------------------------------------------------------
#define SQ_LD 72
#define SR_LD 72
#define SV_LD 72
#define SAL_LD 136
#define P2_SMEM_BYTES ((64*SQ_LD + 128*SR_LD + 128*SV_LD + 64*SAL_LD)*2 + 64*4)

__global__ void __launch_bounds__(512) pass2_fused(
    const __half* __restrict__ Qp,     // [B,H,L,DH] fp16
    const float*  __restrict__ relk,   // [L,L,DH] fp32
    const float*  __restrict__ relv,
    __half* __restrict__ logits,       // [BH,L,L] in: QK fp16; out: alpha' fp16
    const unsigned char* __restrict__ mask,
    __half* __restrict__ ctx,          // [B,H,L,DH] out: AR' fp16
    float* __restrict__ invs)          // [BH,L]
{
    extern __shared__ __half smh[];
    __half (*sQ)[SQ_LD]   = (__half(*)[SQ_LD])smh;
    __half (*sR)[SR_LD]   = (__half(*)[SR_LD])(smh + 64*SQ_LD);
    __half (*sV)[SV_LD]   = (__half(*)[SV_LD])(smh + 64*SQ_LD + 128*SR_LD);
    __half (*sAL)[SAL_LD] = (__half(*)[SAL_LD])(smh + 64*SQ_LD + 128*SR_LD + 128*SV_LD);
    float* rsum = (float*)(smh + 64*SQ_LD + 128*SR_LD + 128*SV_LD + 64*SAL_LD);

    const int q    = blockIdx.x;
    const int tid  = threadIdx.x;
    const int lane = tid & 31;
    const int wid  = tid >> 5;
    const int wm   = (wid & 3) * 16;
    const int wn   = (wid >> 2) * 32;   // QR col group
    const int wnA  = (wid >> 2) * 16;   // AR col group

    const long long LL = (long long)LSEQ * LSEQ;

    const uint32_t sQ_base  = (uint32_t)__cvta_generic_to_shared(&sQ[0][0]);
    const uint32_t sR_base  = (uint32_t)__cvta_generic_to_shared(&sR[0][0]);
    const uint32_t sV_base  = (uint32_t)__cvta_generic_to_shared(&sV[0][0]);
    const uint32_t sAL_base = (uint32_t)__cvta_generic_to_shared(&sAL[0][0]);
    const int a_row = (lane & 7) + ((lane >> 3) & 1) * 8;
    const int a_k8  = ((lane >> 4) & 1) * 8;
    const int b_row = (lane & 7) + ((lane >> 4) & 1) * 8;
    const int b_k8  = ((lane >> 3) & 1) * 8;
    const int t_k   = (lane & 7) + ((lane >> 3) & 1) * 8;
    const int t_n8  = ((lane >> 4) & 1) * 8;

    // Load Q rows (fp16 global): 64 bh x 64 d
    {
        int r = tid >> 3, c = (tid & 7) << 3;
        *(uint4*)&sQ[r][c] =
            *(const uint4*)(Qp + (long long)r*(LSEQ*DHD) + (long long)q*DHD + c);
    }
    if (tid < 64) rsum[tid] = 0.f;

    const float* relkq = relk + (long long)q * (LSEQ*DHD);
    const float* relvq = relv + (long long)q * (LSEQ*DHD);

    float4 fR[4], fV[4];
    auto ldchunk = [&](int kc) {
        #pragma unroll
        for (int i = 0; i < 2; i++) {
            int idx = tid + i*512;
            int r = idx >> 3, c = (idx & 7) << 3;
            const float* pk_ = relkq + (long long)(kc*128 + r)*DHD + c;
            const float* pv_ = relvq + (long long)(kc*128 + r)*DHD + c;
            fR[2*i]   = *(const float4*)pk_;
            fR[2*i+1] = *(const float4*)(pk_ + 4);
            fV[2*i]   = *(const float4*)pv_;
            fV[2*i+1] = *(const float4*)(pv_ + 4);
        }
    };
    auto stchunk = [&]() {
        #pragma unroll
        for (int i = 0; i < 2; i++) {
            int idx = tid + i*512;
            int r = idx >> 3, c = (idx & 7) << 3;
            *(uint4*)&sR[r][c] = make_uint4(
                h2pack(fR[2*i].x, fR[2*i].y),   h2pack(fR[2*i].z, fR[2*i].w),
                h2pack(fR[2*i+1].x, fR[2*i+1].y), h2pack(fR[2*i+1].z, fR[2*i+1].w));
            *(uint4*)&sV[r][c] = make_uint4(
                h2pack(fV[2*i].x, fV[2*i].y),   h2pack(fV[2*i].z, fV[2*i].w),
                h2pack(fV[2*i+1].x, fV[2*i+1].y), h2pack(fV[2*i+1].z, fV[2*i+1].w));
        }
    };

    float ctxr[2][4];
    #pragma unroll
    for (int ni = 0; ni < 2; ni++)
        #pragma unroll
        for (int r = 0; r < 4; r++) ctxr[ni][r] = 0.f;
    float rs[2] = {0.f, 0.f};

    ldchunk(0);

    for (int kc = 0; kc < 8; kc++) {
        const int k0 = kc * 128;
        __syncthreads();                  // prev MMAs done reading sR/sV/sAL
        stchunk();
        __syncthreads();
        if (kc + 1 < 8) ldchunk(kc + 1);  // prefetch next chunk

        const int rowb = wm + (lane >> 2);
        // hoist logits + mask loads (in flight during QR MMA)
        uint32_t lgh[4][2];
        uchar2 mm[4][2];
        #pragma unroll
        for (int ni = 0; ni < 4; ni++) {
            int n_g = k0 + wn + ni*8 + ((lane & 3) << 1);
            #pragma unroll
            for (int h2 = 0; h2 < 2; h2++) {
                int row = rowb + h2*8;
                lgh[ni][h2] = *(const uint32_t*)(logits + (long long)row*LL + (long long)q*LSEQ + n_g);
                mm[ni][h2]  = *(const uchar2*)(mask + (long long)(row >> 4)*LL + (long long)q*LSEQ + n_g);
            }
        }

        // QR MMA: S[64][128] chunk (contraction d=64, 4 k16 steps)
        float S[4][4];
        #pragma unroll
        for (int ni = 0; ni < 4; ni++)
            #pragma unroll
            for (int r = 0; r < 4; r++) S[ni][r] = 0.f;

        #pragma unroll
        for (int kk = 0; kk < 64; kk += 16) {
            uint32_t af[4], bf[4][2];
            ldsm_x4(af, sQ_base + (((wm + a_row)*SQ_LD + kk + a_k8) << 1));
            #pragma unroll
            for (int np = 0; np < 4; np += 2)
                ldsm_x4(&bf[np][0],
                    sR_base + (((wn + np*8 + b_row)*SR_LD + kk + b_k8) << 1));
            #pragma unroll
            for (int ni = 0; ni < 4; ni++)
                mma16(S[ni], af, bf[ni]);
        }

        // combine + exp; write alpha' (global fp16 + smem fp16)
        #pragma unroll
        for (int ni = 0; ni < 4; ni++) {
            int colL = wn + ni*8 + ((lane & 3) << 1);
            #pragma unroll
            for (int h2 = 0; h2 < 2; h2++) {
                int row = rowb + h2*8;
                float2 lg = __half22float2(*(const __half2*)&lgh[ni][h2]);
                float vx = S[ni][h2*2 + 0] + lg.x;
                float vy = S[ni][h2*2 + 1] + lg.y;
                if (mm[ni][h2].x) vx = -10000.f;
                if (mm[ni][h2].y) vy = -10000.f;
                float ex = __expf(vx);
                float ey = __expf(vy);
                rs[h2] += ex + ey;
                __half2 eh = __floats2half2_rn(ex, ey);
                *(__half2*)(logits + (long long)row*LL + (long long)q*LSEQ + k0 + colL) = eh;
                *(__half2*)&sAL[row][colL] = eh;
            }
        }
        __syncthreads();

        // AR MMA: ctxr += alpha'[64][128] * relv[q][k0:k0+128][:] (8 k16 steps)
        #pragma unroll
        for (int kk = 0; kk < 128; kk += 16) {
            uint32_t af[4], bf[2][2];
            ldsm_x4(af, sAL_base + (((wm + a_row)*SAL_LD + kk + a_k8) << 1));
            ldsm_x4_t(&bf[0][0], sV_base + (((kk + t_k)*SV_LD + wnA + t_n8) << 1));
            #pragma unroll
            for (int ni = 0; ni < 2; ni++)
                mma16(ctxr[ni], af, bf[ni]);
        }
    }

    // reduce row sums -> invs
    #pragma unroll
    for (int h2 = 0; h2 < 2; h2++) {
        float v = rs[h2];
        v += __shfl_xor_sync(0xffffffffu, v, 1);
        v += __shfl_xor_sync(0xffffffffu, v, 2);
        if ((lane & 3) == 0)
            atomicAdd(&rsum[wm + (lane >> 2) + h2*8], v);
    }
    __syncthreads();
    if (tid < 64) invs[(long long)tid*LSEQ + q] = 1.f / rsum[tid];

    // write unnormalized AR' to ctx[bh][q][d] (fp16)
    #pragma unroll
    for (int ni = 0; ni < 2; ni++) {
        #pragma unroll
        for (int h2 = 0; h2 < 2; h2++) {
            int row = wm + (lane >> 2) + h2*8;
            int col = wnA + ni*8 + ((lane & 3) << 1);
            *(__half2*)(ctx + (long long)row*(LSEQ*DHD) + (long long)q*DHD + col) =
                __floats2half2_rn(ctxr[ni][h2*2 + 0], ctxr[ni][h2*2 + 1]);
        }
    }
}

extern "C" void kernel_launch(void* const* d_in, const int* in_sizes, int n_in,
                              void* d_out, int out_size)
{
    const float* key   = (const float*)d_in[0];
    const float* value = (const float*)d_in[1];
    const float* query = (const float*)d_in[2];
    const unsigned char* mask = (const unsigned char*)d_in[3];
    const float* rel_k = (const float*)d_in[4];
    const float* rel_v = (const float*)d_in[5];
    const float* Wk = (const float*)d_in[6];
    const float* bk = (const float*)d_in[7];
    const float* Wv = (const float*)d_in[8];
    const float* bv = (const float*)d_in[9];
    const float* Wq = (const float*)d_in[10];
    const float* bq = (const float*)d_in[11];
    const float* Wo = (const float*)d_in[12];
    const float* bo = (const float*)d_in[13];
    float* out = (float*)d_out;

    __half *pq, *pk, *pv, *pctx, *plog;
    float *pinvs;
    cudaGetSymbolAddress((void**)&pq,    g_q);
    cudaGetSymbolAddress((void**)&pk,    g_k);
    cudaGetSymbolAddress((void**)&pv,    g_v);
    cudaGetSymbolAddress((void**)&pctx,  g_ctx);
    cudaGetSymbolAddress((void**)&plog,  g_logits);
    cudaGetSymbolAddress((void**)&pinvs, g_invs);

    const long long LL = (long long)LSEQ * LSEQ;
    const long long LD = (long long)LSEQ * DHD;

    static int attr_done = 0;
    if (!attr_done) {
        cudaFuncSetAttribute(pass2_fused,
            cudaFuncAttributeMaxDynamicSharedMemorySize, P2_SMEM_BYTES);
        attr_done = 1;
    }

    // 1-3: QKV projections fp32->fp16 [B,H,L,DH]
    gemm_h<float,float,__half,128,128,4,4,0,0,1,0><<<dim3(8,32,1), 512>>>(
        key,   Wk, bk, pk, DMODEL, DMODEL, DMODEL, 0, 0, 0, 0, 1.0f, nullptr);
    gemm_h<float,float,__half,128,128,4,4,0,0,1,0><<<dim3(8,32,1), 512>>>(
        value, Wv, bv, pv, DMODEL, DMODEL, DMODEL, 0, 0, 0, 0, 1.0f, nullptr);
    gemm_h<float,float,__half,128,128,4,4,0,0,1,0><<<dim3(8,32,1), 512>>>(
        query, Wq, bq, pq, DMODEL, DMODEL, DMODEL, 0, 0, 0, 0, 0.125f, nullptr);

    // 4: QK logits (fp16 in/out): logits = Q·K^T
    gemm_h<__half,__half,__half,128,128,4,4,0,0,0,0><<<dim3(8,8,BHN), 512>>>(
        pq, pk, nullptr, plog, DHD,
        DHD, DHD, LSEQ,
        LD, LD, LL,
        1.0f, nullptr);

    // 5: fused QR + mask + softmax(no-max) + AR -> alpha' in plog, AR' in pctx
    pass2_fused<<<1024, 512, P2_SMEM_BYTES>>>(pq, rel_k, rel_v, plog, mask, pctx, pinvs);

    // 6: AV: ctx = (alpha'·V + AR') * inv_s   (BMODE=1: V K-major, trans ldsm)
    gemm_h<__half,__half,__half,128,64,8,2,0,1,0,2><<<dim3(1,8,BHN), 512>>>(
        plog, pv, nullptr, pctx, LSEQ,
        LSEQ, DHD, DHD,
        LL, LD, LD,
        1.0f, pinvs);

    // 7: out = ctx @ Wo^T + bo (fp32 output)
    gemm_h<__half,float,float,128,128,4,4,1,0,0,0><<<dim3(8,32,1), 512>>>(
        pctx, Wo, bo, out, DMODEL,
        0, DMODEL, DMODEL,
        0, 0, 0,
        1.0f, nullptr);
}

// round 11
// speedup vs baseline: 1.9611x; 1.0452x over previous
#include <cuda_runtime.h>
#include <cuda_fp16.h>
#include <cstdint>

#define BATCH 4
#define LSEQ  1024
#define DMODEL 1024
#define NH    16
#define DHD   64
#define BHN   (BATCH*NH)        // 64
#define PROJ_ELEMS (BATCH*NH*LSEQ*DHD)
#define LOGIT_ELEMS ((size_t)BHN*LSEQ*LSEQ)

// fp16 intermediates
__device__ __half g_q[PROJ_ELEMS];
__device__ __half g_k[PROJ_ELEMS];
__device__ __half g_v[PROJ_ELEMS];
__device__ __half g_ctx[PROJ_ELEMS];
__device__ __half g_logits[LOGIT_ELEMS];
__device__ float  g_invs[BHN*LSEQ];

__device__ __forceinline__ uint32_t h2pack(float x, float y) {
    __half2 h = __floats2half2_rn(x, y);
    return *(uint32_t*)&h;
}

__device__ __forceinline__ void mma16(float* c, const uint32_t* a, const uint32_t* b) {
    asm volatile(
        "mma.sync.aligned.m16n8k16.row.col.f32.f16.f16.f32 "
        "{%0,%1,%2,%3}, {%4,%5,%6,%7}, {%8,%9}, {%0,%1,%2,%3};"
        : "+f"(c[0]), "+f"(c[1]), "+f"(c[2]), "+f"(c[3])
        : "r"(a[0]), "r"(a[1]), "r"(a[2]), "r"(a[3]), "r"(b[0]), "r"(b[1]));
}

__device__ __forceinline__ void ldsm_x4(uint32_t* r, uint32_t a) {
    asm volatile("ldmatrix.sync.aligned.m8n8.x4.shared.b16 {%0,%1,%2,%3}, [%4];"
        : "=r"(r[0]), "=r"(r[1]), "=r"(r[2]), "=r"(r[3]) : "r"(a));
}
__device__ __forceinline__ void ldsm_x4_t(uint32_t* r, uint32_t a) {
    asm volatile("ldmatrix.sync.aligned.m8n8.x4.trans.shared.b16 {%0,%1,%2,%3}, [%4];"
        : "=r"(r[0]), "=r"(r[1]), "=r"(r[2]), "=r"(r[3]) : "r"(a));
}

__device__ __forceinline__ void cpa16(void* smem, const void* gmem) {
    uint32_t s = (uint32_t)__cvta_generic_to_shared(smem);
    asm volatile("cp.async.cg.shared.global [%0], [%1], 16;" :: "r"(s), "l"(gmem) : "memory");
}

// ---------------------------------------------------------------------------
// Shared GEMM body. fp16-in / fp32-acc / TC-out.
// BMODE 0: C = A * B^T, B stored [N][K]; BMODE 1: C = A * B, B stored [K][N]
// AMODE 1: A gathered from [B,H,L,DH]; CMODE 1: C scattered to [B,H,L,DH]
// EMODE 0: write; EMODE 2: v = (acc + old) * rowscale[r]   (rowscale pre-offset)
// ASYNC (TA and TB both half): cp.async into STAGES-deep dynamic-smem ring.
//   STAGES=1 only valid when K==64 (single tile). STAGES>=3 for pipelining.
// Non-ASYNC (fp32 inputs needing conversion): register prefetch, static smem.
// ---------------------------------------------------------------------------
template<class TA, class TB, class TC, int BM, int BN, int WGM, int WGN,
         int AMODE, int BMODE, int CMODE, int EMODE, int STAGES>
__device__ __forceinline__ void gemm_body(
    const TA* __restrict__ Ap, const TB* __restrict__ Bp,
    const float* __restrict__ bias, TC* __restrict__ Cp,
    int K, long long lda, long long ldb, long long ldc,
    float scale, const float* __restrict__ rowscale, char* dynsm)
{
    constexpr int BK  = 64;
    constexpr int NT  = WGM*WGN*32;
    constexpr int WM  = BM/WGM, WN = BN/WGN;
    constexpr int MI  = WM/16,  NI = WN/8;
    constexpr int AIT = BM*8/NT;
    constexpr int BIT = (BMODE==0) ? BN*8/NT : BK*(BN/8)/NT;
    constexpr int LDA_ = BK + 8;
    constexpr int LDB_ = ((BMODE==0)?BK:BN) + 8;
    constexpr int BROWS = (BMODE==0)?BN:BK;
    constexpr bool ASYNC = (sizeof(TA)==2) && (sizeof(TB)==2);
    constexpr int ASTRIDE = BM*LDA_;
    constexpr int BSTRIDE = BROWS*LDB_;

    const int tid  = threadIdx.x;
    const int lane = tid & 31;
    const int wid  = tid >> 5;
    const int wm   = (wid % WGM) * WM;
    const int wn   = (wid / WGM) * WN;
    const int bm0  = blockIdx.y * BM;
    const int bn0  = blockIdx.x * BN;

    __half* sA;
    __half* sB;
    if constexpr (ASYNC) {
        sA = (__half*)dynsm;
        sB = sA + STAGES*ASTRIDE;
    } else {
        __shared__ __half sAs[ASTRIDE];
        __shared__ __half sBs[BSTRIDE];
        sA = sAs; sB = sBs;
    }

    // ldmatrix per-lane offsets
    const int a_row = (lane & 7) + ((lane >> 3) & 1) * 8;
    const int a_k8  = ((lane >> 4) & 1) * 8;
    const int b_row = (lane & 7) + ((lane >> 4) & 1) * 8;
    const int b_k8  = ((lane >> 3) & 1) * 8;
    const int t_k   = (lane & 7) + ((lane >> 3) & 1) * 8;
    const int t_n8  = ((lane >> 4) & 1) * 8;

    auto aptr = [&](int r, int gk) -> const TA* {
        int grow = bm0 + r;
        if (AMODE == 0) {
            return Ap + (long long)grow*lda + gk;
        } else {
            int b = grow >> 10, l = grow & 1023;
            int hh = gk >> 6,  dd = gk & 63;
            return Ap + (long long)(b*NH + hh)*(LSEQ*DHD) + l*DHD + dd;
        }
    };

    float acc[MI][NI][4];
    #pragma unroll
    for (int mi = 0; mi < MI; mi++)
        #pragma unroll
        for (int ni = 0; ni < NI; ni++)
            #pragma unroll
            for (int r = 0; r < 4; r++) acc[mi][ni][r] = 0.f;

    const int T = K / BK;

    auto compute = [&](int s) {
        const uint32_t sAb = (uint32_t)__cvta_generic_to_shared(sA + s*ASTRIDE);
        const uint32_t sBb = (uint32_t)__cvta_generic_to_shared(sB + s*BSTRIDE);
        #pragma unroll
        for (int kk = 0; kk < BK; kk += 16) {
            uint32_t af[MI][4], bf[NI][2];
            #pragma unroll
            for (int mi = 0; mi < MI; mi++)
                ldsm_x4(af[mi], sAb + (((wm + mi*16 + a_row)*LDA_ + kk + a_k8) << 1));
            #pragma unroll
            for (int np = 0; np < NI; np += 2) {
                if (BMODE == 0)
                    ldsm_x4(&bf[np][0], sBb + (((wn + np*8 + b_row)*LDB_ + kk + b_k8) << 1));
                else
                    ldsm_x4_t(&bf[np][0], sBb + (((kk + t_k)*LDB_ + wn + np*8 + t_n8) << 1));
            }
            #pragma unroll
            for (int mi = 0; mi < MI; mi++)
                #pragma unroll
                for (int ni = 0; ni < NI; ni++)
                    mma16(acc[mi][ni], af[mi], bf[ni]);
        }
    };

    if constexpr (ASYNC) {
        auto cpa_tile = [&](int s, int kt) {
            #pragma unroll
            for (int i = 0; i < AIT; i++) {
                int idx = tid + i*NT;
                int r = idx >> 3, c = (idx & 7) << 3;
                cpa16(sA + s*ASTRIDE + r*LDA_ + c, aptr(r, kt*BK + c));
            }
            #pragma unroll
            for (int i = 0; i < BIT; i++) {
                int idx = tid + i*NT;
                if (BMODE == 0) {
                    int r = idx >> 3, c = (idx & 7) << 3;
                    cpa16(sB + s*BSTRIDE + r*LDB_ + c,
                          Bp + (long long)(bn0 + r)*ldb + kt*BK + c);
                } else {
                    int r = idx / (BN/8), c = (idx % (BN/8)) << 3;
                    cpa16(sB + s*BSTRIDE + r*LDB_ + c,
                          Bp + (long long)(kt*BK + r)*ldb + bn0 + c);
                }
            }
            asm volatile("cp.async.commit_group;" ::: "memory");
        };

        cpa_tile(0, 0);
        if (STAGES > 1 && T > 1) cpa_tile(1, 1);
        for (int t = 0; t < T; ++t) {
            if (STAGES > 1 && t + 1 < T)
                asm volatile("cp.async.wait_group 1;" ::: "memory");
            else
                asm volatile("cp.async.wait_group 0;" ::: "memory");
            __syncthreads();
            compute(t % STAGES);
            if (STAGES > 1 && t + 2 < T) cpa_tile((t + 2) % STAGES, t + 2);
        }
    } else {
        uint4 rga[AIT], rgb[BIT];
        auto loadA = [&](int kt) {
            #pragma unroll
            for (int i = 0; i < AIT; i++) {
                int idx = tid + i*NT;
                int r = idx >> 3, c = (idx & 7) << 3;
                const TA* p = aptr(r, kt*BK + c);
                if constexpr (sizeof(TA) == 4) {
                    float4 u0 = *(const float4*)p;
                    float4 u1 = *(const float4*)(p + 4);
                    rga[i] = make_uint4(h2pack(u0.x,u0.y), h2pack(u0.z,u0.w),
                                        h2pack(u1.x,u1.y), h2pack(u1.z,u1.w));
                } else {
                    rga[i] = *(const uint4*)p;
                }
            }
        };
        auto loadB = [&](int kt) {
            #pragma unroll
            for (int i = 0; i < BIT; i++) {
                int idx = tid + i*NT;
                const TB* p;
                if (BMODE == 0) {
                    int r = idx >> 3, c = (idx & 7) << 3;
                    p = Bp + (long long)(bn0 + r)*ldb + kt*BK + c;
                } else {
                    int r = idx / (BN/8), c = (idx % (BN/8)) << 3;
                    p = Bp + (long long)(kt*BK + r)*ldb + bn0 + c;
                }
                if constexpr (sizeof(TB) == 4) {
                    float4 u0 = *(const float4*)p;
                    float4 u1 = *(const float4*)(p + 4);
                    rgb[i] = make_uint4(h2pack(u0.x,u0.y), h2pack(u0.z,u0.w),
                                        h2pack(u1.x,u1.y), h2pack(u1.z,u1.w));
                } else {
                    rgb[i] = *(const uint4*)p;
                }
            }
        };
        auto stsAB = [&]() {
            #pragma unroll
            for (int i = 0; i < AIT; i++) {
                int idx = tid + i*NT;
                int r = idx >> 3, c = (idx & 7) << 3;
                *(uint4*)&sA[r*LDA_ + c] = rga[i];
            }
            #pragma unroll
            for (int i = 0; i < BIT; i++) {
                int idx = tid + i*NT;
                if (BMODE == 0) {
                    int r = idx >> 3, c = (idx & 7) << 3;
                    *(uint4*)&sB[r*LDB_ + c] = rgb[i];
                } else {
                    int r = idx / (BN/8), c = (idx % (BN/8)) << 3;
                    *(uint4*)&sB[r*LDB_ + c] = rgb[i];
                }
            }
        };

        loadA(0); loadB(0);
        for (int t = 0; t < T; ++t) {
            stsAB();
            __syncthreads();
            if (t + 1 < T) { loadA(t+1); loadB(t+1); }
            compute(0);
            __syncthreads();
        }
    }

    // Epilogue
    #pragma unroll
    for (int mi = 0; mi < MI; mi++) {
        #pragma unroll
        for (int ni = 0; ni < NI; ni++) {
            int mrow = bm0 + wm + mi*16 + (lane >> 2);
            int ncol = bn0 + wn + ni*8 + ((lane & 3) << 1);
            #pragma unroll
            for (int h2 = 0; h2 < 2; h2++) {
                int r = mrow + h2*8;
                float x = acc[mi][ni][h2*2 + 0];
                float y = acc[mi][ni][h2*2 + 1];
                if (bias) { x += bias[ncol]; y += bias[ncol + 1]; }
                x *= scale; y *= scale;
                long long off;
                if (CMODE == 0) {
                    off = (long long)r*ldc + ncol;
                } else {
                    int b = r >> 10, l = r & 1023;
                    int hh = ncol >> 6, dd = ncol & 63;
                    off = (long long)(b*NH + hh)*(LSEQ*DHD) + l*DHD + dd;
                }
                if (EMODE == 2) {
                    float2 o = __half22float2(*(const __half2*)(Cp + off));
                    float iv = rowscale[r];
                    x = (x + o.x) * iv;
                    y = (y + o.y) * iv;
                }
                if constexpr (sizeof(TC) == 4) {
                    *(float2*)(Cp + off) = make_float2(x, y);
                } else {
                    *(__half2*)(Cp + off) = __floats2half2_rn(x, y);
                }
            }
        }
    }
}

template<class TA, class TB, class TC, int BM, int BN, int WGM, int WGN,
         int AMODE, int BMODE, int CMODE, int EMODE, int STAGES = 1, int MINB = 1>
__global__ void __launch_bounds__(WGM*WGN*32, MINB) gemm_h(
    const TA* __restrict__ A, const TB* __restrict__ B,
    const float* __restrict__ bias, TC* __restrict__ C,
    int K,
    long long lda, long long ldb, long long ldc,
    long long sAz, long long sBz, long long sCz,
    float scale, const float* __restrict__ rowscale)
{
    extern __shared__ char dynsm[];
    const int z = blockIdx.z;
    gemm_body<TA,TB,TC,BM,BN,WGM,WGN,AMODE,BMODE,CMODE,EMODE,STAGES>(
        A + (long long)z*sAz, B + (long long)z*sBz, bias, C + (long long)z*sCz,
        K, lda, ldb, ldc, scale,
        rowscale ? rowscale + (long long)z*LSEQ : nullptr, dynsm);
}

// Merged QKV projections: grid.z selects {key,value,query}.
struct P3 {
    const float* A[3];
    const float* W[3];
    const float* b[3];
    __half*      C[3];
    float        s[3];
};
__global__ void __launch_bounds__(512, 1) proj3_kernel(P3 p)
{
    const int z = blockIdx.z;
    gemm_body<float,float,__half,128,128,4,4,0,0,1,0,1>(
        p.A[z], p.W[z], p.b[z], p.C[z],
        DMODEL, DMODEL, DMODEL, DMODEL, p.s[z], nullptr, nullptr);
}

// ---------------------------------------------------------------------------
// Pass 2 (unchanged from r10): per-q fused QR + QK-add + mask + max-free
// softmax + AR. fp16 MMA, register prefetch of next rel chunk.
// ---------------------------------------------------------------------------
#define SQ_LD 72
#define SR_LD 72
#define SV_LD 72
#define SAL_LD 136
#define P2_SMEM_BYTES ((64*SQ_LD + 128*SR_LD + 128*SV_LD + 64*SAL_LD)*2 + 64*4)

__global__ void __launch_bounds__(512) pass2_fused(
    const __half* __restrict__ Qp,
    const float*  __restrict__ relk,
    const float*  __restrict__ relv,
    __half* __restrict__ logits,
    const unsigned char* __restrict__ mask,
    __half* __restrict__ ctx,
    float* __restrict__ invs)
{
    extern __shared__ __half smh[];
    __half (*sQ)[SQ_LD]   = (__half(*)[SQ_LD])smh;
    __half (*sR)[SR_LD]   = (__half(*)[SR_LD])(smh + 64*SQ_LD);
    __half (*sV)[SV_LD]   = (__half(*)[SV_LD])(smh + 64*SQ_LD + 128*SR_LD);
    __half (*sAL)[SAL_LD] = (__half(*)[SAL_LD])(smh + 64*SQ_LD + 128*SR_LD + 128*SV_LD);
    float* rsum = (float*)(smh + 64*SQ_LD + 128*SR_LD + 128*SV_LD + 64*SAL_LD);

    const int q    = blockIdx.x;
    const int tid  = threadIdx.x;
    const int lane = tid & 31;
    const int wid  = tid >> 5;
    const int wm   = (wid & 3) * 16;
    const int wn   = (wid >> 2) * 32;
    const int wnA  = (wid >> 2) * 16;

    const long long LL = (long long)LSEQ * LSEQ;

    const uint32_t sQ_base  = (uint32_t)__cvta_generic_to_shared(&sQ[0][0]);
    const uint32_t sR_base  = (uint32_t)__cvta_generic_to_shared(&sR[0][0]);
    const uint32_t sV_base  = (uint32_t)__cvta_generic_to_shared(&sV[0][0]);
    const uint32_t sAL_base = (uint32_t)__cvta_generic_to_shared(&sAL[0][0]);
    const int a_row = (lane & 7) + ((lane >> 3) & 1) * 8;
    const int a_k8  = ((lane >> 4) & 1) * 8;
    const int b_row = (lane & 7) + ((lane >> 4) & 1) * 8;
    const int b_k8  = ((lane >> 3) & 1) * 8;
    const int t_k   = (lane & 7) + ((lane >> 3) & 1) * 8;
    const int t_n8  = ((lane >> 4) & 1) * 8;

    {
        int r = tid >> 3, c = (tid & 7) << 3;
        *(uint4*)&sQ[r][c] =
            *(const uint4*)(Qp + (long long)r*(LSEQ*DHD) + (long long)q*DHD + c);
    }
    if (tid < 64) rsum[tid] = 0.f;

    const float* relkq = relk + (long long)q * (LSEQ*DHD);
    const float* relvq = relv + (long long)q * (LSEQ*DHD);

    float4 fR[4], fV[4];
    auto ldchunk = [&](int kc) {
        #pragma unroll
        for (int i = 0; i < 2; i++) {
            int idx = tid + i*512;
            int r = idx >> 3, c = (idx & 7) << 3;
            const float* pk_ = relkq + (long long)(kc*128 + r)*DHD + c;
            const float* pv_ = relvq + (long long)(kc*128 + r)*DHD + c;
            fR[2*i]   = *(const float4*)pk_;
            fR[2*i+1] = *(const float4*)(pk_ + 4);
            fV[2*i]   = *(const float4*)pv_;
            fV[2*i+1] = *(const float4*)(pv_ + 4);
        }
    };
    auto stchunk = [&]() {
        #pragma unroll
        for (int i = 0; i < 2; i++) {
            int idx = tid + i*512;
            int r = idx >> 3, c = (idx & 7) << 3;
            *(uint4*)&sR[r][c] = make_uint4(
                h2pack(fR[2*i].x, fR[2*i].y),     h2pack(fR[2*i].z, fR[2*i].w),
                h2pack(fR[2*i+1].x, fR[2*i+1].y), h2pack(fR[2*i+1].z, fR[2*i+1].w));
            *(uint4*)&sV[r][c] = make_uint4(
                h2pack(fV[2*i].x, fV[2*i].y),     h2pack(fV[2*i].z, fV[2*i].w),
                h2pack(fV[2*i+1].x, fV[2*i+1].y), h2pack(fV[2*i+1].z, fV[2*i+1].w));
        }
    };

    float ctxr[2][4];
    #pragma unroll
    for (int ni = 0; ni < 2; ni++)
        #pragma unroll
        for (int r = 0; r < 4; r++) ctxr[ni][r] = 0.f;
    float rs[2] = {0.f, 0.f};

    ldchunk(0);

    for (int kc = 0; kc < 8; kc++) {
        const int k0 = kc * 128;
        __syncthreads();
        stchunk();
        __syncthreads();
        if (kc + 1 < 8) ldchunk(kc + 1);

        const int rowb = wm + (lane >> 2);
        uint32_t lgh[4][2];
        uchar2 mm[4][2];
        #pragma unroll
        for (int ni = 0; ni < 4; ni++) {
            int n_g = k0 + wn + ni*8 + ((lane & 3) << 1);
            #pragma unroll
            for (int h2 = 0; h2 < 2; h2++) {
                int row = rowb + h2*8;
                lgh[ni][h2] = *(const uint32_t*)(logits + (long long)row*LL + (long long)q*LSEQ + n_g);
                mm[ni][h2]  = *(const uchar2*)(mask + (long long)(row >> 4)*LL + (long long)q*LSEQ + n_g);
            }
        }

        float S[4][4];
        #pragma unroll
        for (int ni = 0; ni < 4; ni++)
            #pragma unroll
            for (int r = 0; r < 4; r++) S[ni][r] = 0.f;

        #pragma unroll
        for (int kk = 0; kk < 64; kk += 16) {
            uint32_t af[4], bf[4][2];
            ldsm_x4(af, sQ_base + (((wm + a_row)*SQ_LD + kk + a_k8) << 1));
            #pragma unroll
            for (int np = 0; np < 4; np += 2)
                ldsm_x4(&bf[np][0],
                    sR_base + (((wn + np*8 + b_row)*SR_LD + kk + b_k8) << 1));
            #pragma unroll
            for (int ni = 0; ni < 4; ni++)
                mma16(S[ni], af, bf[ni]);
        }

        #pragma unroll
        for (int ni = 0; ni < 4; ni++) {
            int colL = wn + ni*8 + ((lane & 3) << 1);
            #pragma unroll
            for (int h2 = 0; h2 < 2; h2++) {
                int row = rowb + h2*8;
                float2 lg = __half22float2(*(const __half2*)&lgh[ni][h2]);
                float vx = S[ni][h2*2 + 0] + lg.x;
                float vy = S[ni][h2*2 + 1] + lg.y;
                if (mm[ni][h2].x) vx = -10000.f;
                if (mm[ni][h2].y) vy = -10000.f;
                float ex = __expf(vx);
                float ey = __expf(vy);
                rs[h2] += ex + ey;
                __half2 eh = __floats2half2_rn(ex, ey);
                *(__half2*)(logits + (long long)row*LL + (long long)q*LSEQ + k0 + colL) = eh;
                *(__half2*)&sAL[row][colL] = eh;
            }
        }
        __syncthreads();

        #pragma unroll
        for (int kk = 0; kk < 128; kk += 16) {
            uint32_t af[4], bf[2][2];
            ldsm_x4(af, sAL_base + (((wm + a_row)*SAL_LD + kk + a_k8) << 1));
            ldsm_x4_t(&bf[0][0], sV_base + (((kk + t_k)*SV_LD + wnA + t_n8) << 1));
            #pragma unroll
            for (int ni = 0; ni < 2; ni++)
                mma16(ctxr[ni], af, bf[ni]);
        }
    }

    #pragma unroll
    for (int h2 = 0; h2 < 2; h2++) {
        float v = rs[h2];
        v += __shfl_xor_sync(0xffffffffu, v, 1);
        v += __shfl_xor_sync(0xffffffffu, v, 2);
        if ((lane & 3) == 0)
            atomicAdd(&rsum[wm + (lane >> 2) + h2*8], v);
    }
    __syncthreads();
    if (tid < 64) invs[(long long)tid*LSEQ + q] = 1.f / rsum[tid];

    #pragma unroll
    for (int ni = 0; ni < 2; ni++) {
        #pragma unroll
        for (int h2 = 0; h2 < 2; h2++) {
            int row = wm + (lane >> 2) + h2*8;
            int col = wnA + ni*8 + ((lane & 3) << 1);
            *(__half2*)(ctx + (long long)row*(LSEQ*DHD) + (long long)q*DHD + col) =
                __floats2half2_rn(ctxr[ni][h2*2 + 0], ctxr[ni][h2*2 + 1]);
        }
    }
}

extern "C" void kernel_launch(void* const* d_in, const int* in_sizes, int n_in,
                              void* d_out, int out_size)
{
    const float* key   = (const float*)d_in[0];
    const float* value = (const float*)d_in[1];
    const float* query = (const float*)d_in[2];
    const unsigned char* mask = (const unsigned char*)d_in[3];
    const float* rel_k = (const float*)d_in[4];
    const float* rel_v = (const float*)d_in[5];
    const float* Wk = (const float*)d_in[6];
    const float* bk = (const float*)d_in[7];
    const float* Wv = (const float*)d_in[8];
    const float* bv = (const float*)d_in[9];
    const float* Wq = (const float*)d_in[10];
    const float* bq = (const float*)d_in[11];
    const float* Wo = (const float*)d_in[12];
    const float* bo = (const float*)d_in[13];
    float* out = (float*)d_out;

    __half *pq, *pk, *pv, *pctx, *plog;
    float *pinvs;
    cudaGetSymbolAddress((void**)&pq,    g_q);
    cudaGetSymbolAddress((void**)&pk,    g_k);
    cudaGetSymbolAddress((void**)&pv,    g_v);
    cudaGetSymbolAddress((void**)&pctx,  g_ctx);
    cudaGetSymbolAddress((void**)&plog,  g_logits);
    cudaGetSymbolAddress((void**)&pinvs, g_invs);

    const long long LL = (long long)LSEQ * LSEQ;
    const long long LD = (long long)LSEQ * DHD;

    // dynamic smem: QK (1 stage), AV (3 stages)
    constexpr int QK_SMEM = (128*72 + 128*72) * 2;            // 36,864 B
    constexpr int AV_SMEM = 3 * (128*72 + 64*72) * 2;         // 82,944 B

    auto qk_fn = gemm_h<__half,__half,__half,128,128,4,4,0,0,0,0,1,2>;
    auto av_fn = gemm_h<__half,__half,__half,128,64,8,2,0,1,0,2,3,2>;

    static int attr_done = 0;
    if (!attr_done) {
        cudaFuncSetAttribute(pass2_fused,
            cudaFuncAttributeMaxDynamicSharedMemorySize, P2_SMEM_BYTES);
        cudaFuncSetAttribute(av_fn,
            cudaFuncAttributeMaxDynamicSharedMemorySize, AV_SMEM);
        attr_done = 1;
    }

    // 1: merged QKV projections (grid.z selects k/v/q)
    P3 p;
    p.A[0] = key;   p.W[0] = Wk; p.b[0] = bk; p.C[0] = pk; p.s[0] = 1.0f;
    p.A[1] = value; p.W[1] = Wv; p.b[1] = bv; p.C[1] = pv; p.s[1] = 1.0f;
    p.A[2] = query; p.W[2] = Wq; p.b[2] = bq; p.C[2] = pq; p.s[2] = 0.125f;
    proj3_kernel<<<dim3(8,32,3), 512>>>(p);

    // 2: QK logits = Q·K^T (cp.async, 2 blocks/SM)
    qk_fn<<<dim3(8,8,BHN), 512, QK_SMEM>>>(
        pq, pk, nullptr, plog, DHD,
        DHD, DHD, LSEQ,
        LD, LD, LL,
        1.0f, nullptr);

    // 3: fused QR + mask + softmax(no-max) + AR -> alpha' in plog, AR' in pctx
    pass2_fused<<<1024, 512, P2_SMEM_BYTES>>>(pq, rel_k, rel_v, plog, mask, pctx, pinvs);

    // 4: AV: ctx = (alpha'·V + AR') * inv_s  (cp.async 3-stage, 2 blocks/SM)
    av_fn<<<dim3(1,8,BHN), 512, AV_SMEM>>>(
        plog, pv, nullptr, pctx, LSEQ,
        LSEQ, DHD, DHD,
        LL, LD, LD,
        1.0f, pinvs);

    // 5: out = ctx @ Wo^T + bo (fp32 output)
    gemm_h<__half,float,float,128,128,4,4,1,0,0,0,1,1><<<dim3(8,32,1), 512>>>(
        pctx, Wo, bo, out, DMODEL,
        0, DMODEL, DMODEL,
        0, 0, 0,
        1.0f, nullptr);
}

// round 12
// speedup vs baseline: 2.3668x; 1.2069x over previous
#include <cuda_runtime.h>
#include <cuda_fp16.h>
#include <cstdint>

#define BATCH 4
#define LSEQ  1024
#define DMODEL 1024
#define NH    16
#define DHD   64
#define BHN   (BATCH*NH)        // 64
#define PROJ_ELEMS (BATCH*NH*LSEQ*DHD)
#define LOGIT_ELEMS ((size_t)BHN*LSEQ*LSEQ)
#define WELEMS (DMODEL*DMODEL)

// fp16 intermediates
__device__ __half g_q[PROJ_ELEMS];
__device__ __half g_k[PROJ_ELEMS];
__device__ __half g_v[PROJ_ELEMS];
__device__ __half g_ctx[PROJ_ELEMS];
__device__ __half g_logits[LOGIT_ELEMS];
__device__ float  g_invs[BHN*LSEQ];
// fp16 copies of fp32 inputs/weights (converted once per launch)
__device__ __half g_hkey[PROJ_ELEMS];
__device__ __half g_hval[PROJ_ELEMS];
__device__ __half g_hqin[PROJ_ELEMS];
__device__ __half g_hwk[WELEMS];
__device__ __half g_hwv[WELEMS];
__device__ __half g_hwq[WELEMS];
__device__ __half g_hwo[WELEMS];

__device__ __forceinline__ uint32_t h2pack(float x, float y) {
    __half2 h = __floats2half2_rn(x, y);
    return *(uint32_t*)&h;
}

__device__ __forceinline__ void mma16(float* c, const uint32_t* a, const uint32_t* b) {
    asm volatile(
        "mma.sync.aligned.m16n8k16.row.col.f32.f16.f16.f32 "
        "{%0,%1,%2,%3}, {%4,%5,%6,%7}, {%8,%9}, {%0,%1,%2,%3};"
        : "+f"(c[0]), "+f"(c[1]), "+f"(c[2]), "+f"(c[3])
        : "r"(a[0]), "r"(a[1]), "r"(a[2]), "r"(a[3]), "r"(b[0]), "r"(b[1]));
}

__device__ __forceinline__ void ldsm_x4(uint32_t* r, uint32_t a) {
    asm volatile("ldmatrix.sync.aligned.m8n8.x4.shared.b16 {%0,%1,%2,%3}, [%4];"
        : "=r"(r[0]), "=r"(r[1]), "=r"(r[2]), "=r"(r[3]) : "r"(a));
}
__device__ __forceinline__ void ldsm_x4_t(uint32_t* r, uint32_t a) {
    asm volatile("ldmatrix.sync.aligned.m8n8.x4.trans.shared.b16 {%0,%1,%2,%3}, [%4];"
        : "=r"(r[0]), "=r"(r[1]), "=r"(r[2]), "=r"(r[3]) : "r"(a));
}

__device__ __forceinline__ void cpa16(void* smem, const void* gmem) {
    uint32_t s = (uint32_t)__cvta_generic_to_shared(smem);
    asm volatile("cp.async.cg.shared.global [%0], [%1], 16;" :: "r"(s), "l"(gmem) : "memory");
}
template<int N> __device__ __forceinline__ void cp_wait() {
    asm volatile("cp.async.wait_group %0;" :: "n"(N) : "memory");
}
__device__ __forceinline__ void cp_commit() {
    asm volatile("cp.async.commit_group;" ::: "memory");
}

// ---------------------------------------------------------------------------
// Shared GEMM body. fp16-in / fp32-acc / TC-out.
// BMODE 0: C = A * B^T, B [N][K]; BMODE 1: C = A * B, B [K][N]
// AMODE 1: A gathered from [B,H,L,DH]; CMODE 1: C scattered to [B,H,L,DH]
// EMODE 0: write; EMODE 2: v = (acc + old) * rowscale[r]
// All-fp16 operands use a STAGES-deep cp.async ring in dynamic smem.
// ---------------------------------------------------------------------------
template<class TA, class TB, class TC, int BM, int BN, int WGM, int WGN,
         int AMODE, int BMODE, int CMODE, int EMODE, int STAGES>
__device__ __forceinline__ void gemm_body(
    const TA* __restrict__ Ap, const TB* __restrict__ Bp,
    const float* __restrict__ bias, TC* __restrict__ Cp,
    int K, long long lda, long long ldb, long long ldc,
    float scale, const float* __restrict__ rowscale, char* dynsm)
{
    constexpr int BK  = 64;
    constexpr int NT  = WGM*WGN*32;
    constexpr int WM  = BM/WGM, WN = BN/WGN;
    constexpr int MI  = WM/16,  NI = WN/8;
    constexpr int AIT = BM*8/NT;
    constexpr int BIT = (BMODE==0) ? BN*8/NT : BK*(BN/8)/NT;
    constexpr int LDA_ = BK + 8;
    constexpr int LDB_ = ((BMODE==0)?BK:BN) + 8;
    constexpr int BROWS = (BMODE==0)?BN:BK;
    constexpr int ASTRIDE = BM*LDA_;
    constexpr int BSTRIDE = BROWS*LDB_;
    constexpr int D = STAGES - 1;

    const int tid  = threadIdx.x;
    const int lane = tid & 31;
    const int wid  = tid >> 5;
    const int wm   = (wid % WGM) * WM;
    const int wn   = (wid / WGM) * WN;
    const int bm0  = blockIdx.y * BM;
    const int bn0  = blockIdx.x * BN;

    __half* sA = (__half*)dynsm;
    __half* sB = sA + STAGES*ASTRIDE;

    const int a_row = (lane & 7) + ((lane >> 3) & 1) * 8;
    const int a_k8  = ((lane >> 4) & 1) * 8;
    const int b_row = (lane & 7) + ((lane >> 4) & 1) * 8;
    const int b_k8  = ((lane >> 3) & 1) * 8;
    const int t_k   = (lane & 7) + ((lane >> 3) & 1) * 8;
    const int t_n8  = ((lane >> 4) & 1) * 8;

    auto aptr = [&](int r, int gk) -> const TA* {
        int grow = bm0 + r;
        if (AMODE == 0) {
            return Ap + (long long)grow*lda + gk;
        } else {
            int b = grow >> 10, l = grow & 1023;
            int hh = gk >> 6,  dd = gk & 63;
            return Ap + (long long)(b*NH + hh)*(LSEQ*DHD) + l*DHD + dd;
        }
    };

    float acc[MI][NI][4];
    #pragma unroll
    for (int mi = 0; mi < MI; mi++)
        #pragma unroll
        for (int ni = 0; ni < NI; ni++)
            #pragma unroll
            for (int r = 0; r < 4; r++) acc[mi][ni][r] = 0.f;

    const int T = K / BK;

    auto compute = [&](int s) {
        const uint32_t sAb = (uint32_t)__cvta_generic_to_shared(sA + s*ASTRIDE);
        const uint32_t sBb = (uint32_t)__cvta_generic_to_shared(sB + s*BSTRIDE);
        #pragma unroll
        for (int kk = 0; kk < BK; kk += 16) {
            uint32_t af[MI][4], bf[NI][2];
            #pragma unroll
            for (int mi = 0; mi < MI; mi++)
                ldsm_x4(af[mi], sAb + (((wm + mi*16 + a_row)*LDA_ + kk + a_k8) << 1));
            #pragma unroll
            for (int np = 0; np < NI; np += 2) {
                if (BMODE == 0)
                    ldsm_x4(&bf[np][0], sBb + (((wn + np*8 + b_row)*LDB_ + kk + b_k8) << 1));
                else
                    ldsm_x4_t(&bf[np][0], sBb + (((kk + t_k)*LDB_ + wn + np*8 + t_n8) << 1));
            }
            #pragma unroll
            for (int mi = 0; mi < MI; mi++)
                #pragma unroll
                for (int ni = 0; ni < NI; ni++)
                    mma16(acc[mi][ni], af[mi], bf[ni]);
        }
    };

    auto cpa_tile = [&](int s, int kt) {
        #pragma unroll
        for (int i = 0; i < AIT; i++) {
            int idx = tid + i*NT;
            int r = idx >> 3, c = (idx & 7) << 3;
            cpa16(sA + s*ASTRIDE + r*LDA_ + c, aptr(r, kt*BK + c));
        }
        #pragma unroll
        for (int i = 0; i < BIT; i++) {
            int idx = tid + i*NT;
            if (BMODE == 0) {
                int r = idx >> 3, c = (idx & 7) << 3;
                cpa16(sB + s*BSTRIDE + r*LDB_ + c,
                      Bp + (long long)(bn0 + r)*ldb + kt*BK + c);
            } else {
                int r = idx / (BN/8), c = (idx % (BN/8)) << 3;
                cpa16(sB + s*BSTRIDE + r*LDB_ + c,
                      Bp + (long long)(kt*BK + r)*ldb + bn0 + c);
            }
        }
        cp_commit();
    };

    if constexpr (STAGES == 1) {
        cpa_tile(0, 0);
        cp_wait<0>();
        __syncthreads();
        compute(0);   // K must equal BK
    } else {
        #pragma unroll
        for (int s = 0; s < D; s++)
            if (s < T) cpa_tile(s, s);
        for (int t = 0; t < T; ++t) {
            if (t + D < T) cp_wait<(D > 0 ? D - 1 : 0)>();
            else           cp_wait<0>();
            __syncthreads();
            if (t + D < T) cpa_tile((t + D) % STAGES, t + D);
            compute(t % STAGES);
        }
    }

    // Epilogue
    #pragma unroll
    for (int mi = 0; mi < MI; mi++) {
        #pragma unroll
        for (int ni = 0; ni < NI; ni++) {
            int mrow = bm0 + wm + mi*16 + (lane >> 2);
            int ncol = bn0 + wn + ni*8 + ((lane & 3) << 1);
            #pragma unroll
            for (int h2 = 0; h2 < 2; h2++) {
                int r = mrow + h2*8;
                float x = acc[mi][ni][h2*2 + 0];
                float y = acc[mi][ni][h2*2 + 1];
                if (bias) { x += bias[ncol]; y += bias[ncol + 1]; }
                x *= scale; y *= scale;
                long long off;
                if (CMODE == 0) {
                    off = (long long)r*ldc + ncol;
                } else {
                    int b = r >> 10, l = r & 1023;
                    int hh = ncol >> 6, dd = ncol & 63;
                    off = (long long)(b*NH + hh)*(LSEQ*DHD) + l*DHD + dd;
                }
                if (EMODE == 2) {
                    float2 o = __half22float2(*(const __half2*)(Cp + off));
                    float iv = rowscale[r];
                    x = (x + o.x) * iv;
                    y = (y + o.y) * iv;
                }
                if constexpr (sizeof(TC) == 4) {
                    *(float2*)(Cp + off) = make_float2(x, y);
                } else {
                    *(__half2*)(Cp + off) = __floats2half2_rn(x, y);
                }
            }
        }
    }
}

template<class TA, class TB, class TC, int BM, int BN, int WGM, int WGN,
         int AMODE, int BMODE, int CMODE, int EMODE, int STAGES, int MINB>
__global__ void __launch_bounds__(WGM*WGN*32, MINB) gemm_h(
    const TA* __restrict__ A, const TB* __restrict__ B,
    const float* __restrict__ bias, TC* __restrict__ C,
    int K,
    long long lda, long long ldb, long long ldc,
    long long sAz, long long sBz, long long sCz,
    float scale, const float* __restrict__ rowscale)
{
    extern __shared__ char dynsm[];
    const int z = blockIdx.z;
    gemm_body<TA,TB,TC,BM,BN,WGM,WGN,AMODE,BMODE,CMODE,EMODE,STAGES>(
        A + (long long)z*sAz, B + (long long)z*sBz, bias, C + (long long)z*sCz,
        K, lda, ldb, ldc, scale,
        rowscale ? rowscale + (long long)z*LSEQ : nullptr, dynsm);
}

// Merged QKV projections (all-fp16, cp.async pipelined): grid.z selects k/v/q.
struct P3 {
    const __half* A[3];
    const __half* W[3];
    const float*  b[3];
    __half*       C[3];
    float         s[3];
};
__global__ void __launch_bounds__(512, 2) proj3_kernel(P3 p)
{
    extern __shared__ char dynsm[];
    const int z = blockIdx.z;
    gemm_body<__half,__half,__half,128,128,4,4,0,0,1,0,3>(
        p.A[z], p.W[z], p.b[z], p.C[z],
        DMODEL, DMODEL, DMODEL, DMODEL, p.s[z], nullptr, dynsm);
}

// fp32 -> fp16 conversion, 7 segments (3 inputs + 4 weights)
struct Cvt7 {
    const float* s[7];
    __half*      d[7];
    int          n4[7];   // float4 count
};
__global__ void __launch_bounds__(256) cvt7_kernel(Cvt7 c)
{
    int seg = blockIdx.y;
    const float4* src = (const float4*)c.s[seg];
    __half* dst = c.d[seg];
    int n4 = c.n4[seg];
    for (int i = blockIdx.x*blockDim.x + threadIdx.x; i < n4;
         i += gridDim.x*blockDim.x) {
        float4 v = src[i];
        uint2 o = make_uint2(h2pack(v.x, v.y), h2pack(v.z, v.w));
        *(uint2*)(dst + (size_t)i*4) = o;
    }
}

// ---------------------------------------------------------------------------
// Pass 2 (unchanged): per-q fused QR + QK-add + mask + max-free softmax + AR.
// ---------------------------------------------------------------------------
#define SQ_LD 72
#define SR_LD 72
#define SV_LD 72
#define SAL_LD 136
#define P2_SMEM_BYTES ((64*SQ_LD + 128*SR_LD + 128*SV_LD + 64*SAL_LD)*2 + 64*4)

__global__ void __launch_bounds__(512) pass2_fused(
    const __half* __restrict__ Qp,
    const float*  __restrict__ relk,
    const float*  __restrict__ relv,
    __half* __restrict__ logits,
    const unsigned char* __restrict__ mask,
    __half* __restrict__ ctx,
    float* __restrict__ invs)
{
    extern __shared__ __half smh[];
    __half (*sQ)[SQ_LD]   = (__half(*)[SQ_LD])smh;
    __half (*sR)[SR_LD]   = (__half(*)[SR_LD])(smh + 64*SQ_LD);
    __half (*sV)[SV_LD]   = (__half(*)[SV_LD])(smh + 64*SQ_LD + 128*SR_LD);
    __half (*sAL)[SAL_LD] = (__half(*)[SAL_LD])(smh + 64*SQ_LD + 128*SR_LD + 128*SV_LD);
    float* rsum = (float*)(smh + 64*SQ_LD + 128*SR_LD + 128*SV_LD + 64*SAL_LD);

    const int q    = blockIdx.x;
    const int tid  = threadIdx.x;
    const int lane = tid & 31;
    const int wid  = tid >> 5;
    const int wm   = (wid & 3) * 16;
    const int wn   = (wid >> 2) * 32;
    const int wnA  = (wid >> 2) * 16;

    const long long LL = (long long)LSEQ * LSEQ;

    const uint32_t sQ_base  = (uint32_t)__cvta_generic_to_shared(&sQ[0][0]);
    const uint32_t sR_base  = (uint32_t)__cvta_generic_to_shared(&sR[0][0]);
    const uint32_t sV_base  = (uint32_t)__cvta_generic_to_shared(&sV[0][0]);
    const uint32_t sAL_base = (uint32_t)__cvta_generic_to_shared(&sAL[0][0]);
    const int a_row = (lane & 7) + ((lane >> 3) & 1) * 8;
    const int a_k8  = ((lane >> 4) & 1) * 8;
    const int b_row = (lane & 7) + ((lane >> 4) & 1) * 8;
    const int b_k8  = ((lane >> 3) & 1) * 8;
    const int t_k   = (lane & 7) + ((lane >> 3) & 1) * 8;
    const int t_n8  = ((lane >> 4) & 1) * 8;

    {
        int r = tid >> 3, c = (tid & 7) << 3;
        *(uint4*)&sQ[r][c] =
            *(const uint4*)(Qp + (long long)r*(LSEQ*DHD) + (long long)q*DHD + c);
    }
    if (tid < 64) rsum[tid] = 0.f;

    const float* relkq = relk + (long long)q * (LSEQ*DHD);
    const float* relvq = relv + (long long)q * (LSEQ*DHD);

    float4 fR[4], fV[4];
    auto ldchunk = [&](int kc) {
        #pragma unroll
        for (int i = 0; i < 2; i++) {
            int idx = tid + i*512;
            int r = idx >> 3, c = (idx & 7) << 3;
            const float* pk_ = relkq + (long long)(kc*128 + r)*DHD + c;
            const float* pv_ = relvq + (long long)(kc*128 + r)*DHD + c;
            fR[2*i]   = *(const float4*)pk_;
            fR[2*i+1] = *(const float4*)(pk_ + 4);
            fV[2*i]   = *(const float4*)pv_;
            fV[2*i+1] = *(const float4*)(pv_ + 4);
        }
    };
    auto stchunk = [&]() {
        #pragma unroll
        for (int i = 0; i < 2; i++) {
            int idx = tid + i*512;
            int r = idx >> 3, c = (idx & 7) << 3;
            *(uint4*)&sR[r][c] = make_uint4(
                h2pack(fR[2*i].x, fR[2*i].y),     h2pack(fR[2*i].z, fR[2*i].w),
                h2pack(fR[2*i+1].x, fR[2*i+1].y), h2pack(fR[2*i+1].z, fR[2*i+1].w));
            *(uint4*)&sV[r][c] = make_uint4(
                h2pack(fV[2*i].x, fV[2*i].y),     h2pack(fV[2*i].z, fV[2*i].w),
                h2pack(fV[2*i+1].x, fV[2*i+1].y), h2pack(fV[2*i+1].z, fV[2*i+1].w));
        }
    };

    float ctxr[2][4];
    #pragma unroll
    for (int ni = 0; ni < 2; ni++)
        #pragma unroll
        for (int r = 0; r < 4; r++) ctxr[ni][r] = 0.f;
    float rs[2] = {0.f, 0.f};

    ldchunk(0);

    for (int kc = 0; kc < 8; kc++) {
        const int k0 = kc * 128;
        __syncthreads();
        stchunk();
        __syncthreads();
        if (kc + 1 < 8) ldchunk(kc + 1);

        const int rowb = wm + (lane >> 2);
        uint32_t lgh[4][2];
        uchar2 mm[4][2];
        #pragma unroll
        for (int ni = 0; ni < 4; ni++) {
            int n_g = k0 + wn + ni*8 + ((lane & 3) << 1);
            #pragma unroll
            for (int h2 = 0; h2 < 2; h2++) {
                int row = rowb + h2*8;
                lgh[ni][h2] = *(const uint32_t*)(logits + (long long)row*LL + (long long)q*LSEQ + n_g);
                mm[ni][h2]  = *(const uchar2*)(mask + (long long)(row >> 4)*LL + (long long)q*LSEQ + n_g);
            }
        }

        float S[4][4];
        #pragma unroll
        for (int ni = 0; ni < 4; ni++)
            #pragma unroll
            for (int r = 0; r < 4; r++) S[ni][r] = 0.f;

        #pragma unroll
        for (int kk = 0; kk < 64; kk += 16) {
            uint32_t af[4], bf[4][2];
            ldsm_x4(af, sQ_base + (((wm + a_row)*SQ_LD + kk + a_k8) << 1));
            #pragma unroll
            for (int np = 0; np < 4; np += 2)
                ldsm_x4(&bf[np][0],
                    sR_base + (((wn + np*8 + b_row)*SR_LD + kk + b_k8) << 1));
            #pragma unroll
            for (int ni = 0; ni < 4; ni++)
                mma16(S[ni], af, bf[ni]);
        }

        #pragma unroll
        for (int ni = 0; ni < 4; ni++) {
            int colL = wn + ni*8 + ((lane & 3) << 1);
            #pragma unroll
            for (int h2 = 0; h2 < 2; h2++) {
                int row = rowb + h2*8;
                float2 lg = __half22float2(*(const __half2*)&lgh[ni][h2]);
                float vx = S[ni][h2*2 + 0] + lg.x;
                float vy = S[ni][h2*2 + 1] + lg.y;
                if (mm[ni][h2].x) vx = -10000.f;
                if (mm[ni][h2].y) vy = -10000.f;
                float ex = __expf(vx);
                float ey = __expf(vy);
                rs[h2] += ex + ey;
                __half2 eh = __floats2half2_rn(ex, ey);
                *(__half2*)(logits + (long long)row*LL + (long long)q*LSEQ + k0 + colL) = eh;
                *(__half2*)&sAL[row][colL] = eh;
            }
        }
        __syncthreads();

        #pragma unroll
        for (int kk = 0; kk < 128; kk += 16) {
            uint32_t af[4], bf[2][2];
            ldsm_x4(af, sAL_base + (((wm + a_row)*SAL_LD + kk + a_k8) << 1));
            ldsm_x4_t(&bf[0][0], sV_base + (((kk + t_k)*SV_LD + wnA + t_n8) << 1));
            #pragma unroll
            for (int ni = 0; ni < 2; ni++)
                mma16(ctxr[ni], af, bf[ni]);
        }
    }

    #pragma unroll
    for (int h2 = 0; h2 < 2; h2++) {
        float v = rs[h2];
        v += __shfl_xor_sync(0xffffffffu, v, 1);
        v += __shfl_xor_sync(0xffffffffu, v, 2);
        if ((lane & 3) == 0)
            atomicAdd(&rsum[wm + (lane >> 2) + h2*8], v);
    }
    __syncthreads();
    if (tid < 64) invs[(long long)tid*LSEQ + q] = 1.f / rsum[tid];

    #pragma unroll
    for (int ni = 0; ni < 2; ni++) {
        #pragma unroll
        for (int h2 = 0; h2 < 2; h2++) {
            int row = wm + (lane >> 2) + h2*8;
            int col = wnA + ni*8 + ((lane & 3) << 1);
            *(__half2*)(ctx + (long long)row*(LSEQ*DHD) + (long long)q*DHD + col) =
                __floats2half2_rn(ctxr[ni][h2*2 + 0], ctxr[ni][h2*2 + 1]);
        }
    }
}

extern "C" void kernel_launch(void* const* d_in, const int* in_sizes, int n_in,
                              void* d_out, int out_size)
{
    const float* key   = (const float*)d_in[0];
    const float* value = (const float*)d_in[1];
    const float* query = (const float*)d_in[2];
    const unsigned char* mask = (const unsigned char*)d_in[3];
    const float* rel_k = (const float*)d_in[4];
    const float* rel_v = (const float*)d_in[5];
    const float* Wk = (const float*)d_in[6];
    const float* bk = (const float*)d_in[7];
    const float* Wv = (const float*)d_in[8];
    const float* bv = (const float*)d_in[9];
    const float* Wq = (const float*)d_in[10];
    const float* bq = (const float*)d_in[11];
    const float* Wo = (const float*)d_in[12];
    const float* bo = (const float*)d_in[13];
    float* out = (float*)d_out;

    __half *pq, *pk, *pv, *pctx, *plog;
    __half *hkey, *hval, *hqin, *hwk, *hwv, *hwq, *hwo;
    float *pinvs;
    cudaGetSymbolAddress((void**)&pq,    g_q);
    cudaGetSymbolAddress((void**)&pk,    g_k);
    cudaGetSymbolAddress((void**)&pv,    g_v);
    cudaGetSymbolAddress((void**)&pctx,  g_ctx);
    cudaGetSymbolAddress((void**)&plog,  g_logits);
    cudaGetSymbolAddress((void**)&pinvs, g_invs);
    cudaGetSymbolAddress((void**)&hkey,  g_hkey);
    cudaGetSymbolAddress((void**)&hval,  g_hval);
    cudaGetSymbolAddress((void**)&hqin,  g_hqin);
    cudaGetSymbolAddress((void**)&hwk,   g_hwk);
    cudaGetSymbolAddress((void**)&hwv,   g_hwv);
    cudaGetSymbolAddress((void**)&hwq,   g_hwq);
    cudaGetSymbolAddress((void**)&hwo,   g_hwo);

    const long long LL = (long long)LSEQ * LSEQ;
    const long long LD = (long long)LSEQ * DHD;

    // dynamic smem sizes
    constexpr int P3_SMEM = 3 * (128*72 + 128*72) * 2;   // 110,592 B
    constexpr int QK_SMEM = (128*72 + 128*72) * 2;       //  36,864 B
    constexpr int AV_SMEM = 4 * (128*72 + 64*72) * 2;    // 110,592 B
    constexpr int OUT_SMEM = 3 * (128*72 + 128*72) * 2;  // 110,592 B

    auto qk_fn  = gemm_h<__half,__half,__half,128,128,4,4,0,0,0,0,1,2>;
    auto av_fn  = gemm_h<__half,__half,__half,128,64,8,2,0,1,0,2,4,2>;
    auto out_fn = gemm_h<__half,__half,float,128,128,4,4,1,0,0,0,3,2>;

    static int attr_done = 0;
    if (!attr_done) {
        cudaFuncSetAttribute(pass2_fused,
            cudaFuncAttributeMaxDynamicSharedMemorySize, P2_SMEM_BYTES);
        cudaFuncSetAttribute(proj3_kernel,
            cudaFuncAttributeMaxDynamicSharedMemorySize, P3_SMEM);
        cudaFuncSetAttribute(av_fn,
            cudaFuncAttributeMaxDynamicSharedMemorySize, AV_SMEM);
        cudaFuncSetAttribute(out_fn,
            cudaFuncAttributeMaxDynamicSharedMemorySize, OUT_SMEM);
        attr_done = 1;
    }

    // 0: fp32 -> fp16 conversion of inputs + weights (bit-identical to the
    //    previous in-loop conversion; pure data-movement change)
    Cvt7 cv;
    cv.s[0] = key;   cv.d[0] = hkey; cv.n4[0] = PROJ_ELEMS/4;
    cv.s[1] = value; cv.d[1] = hval; cv.n4[1] = PROJ_ELEMS/4;
    cv.s[2] = query; cv.d[2] = hqin; cv.n4[2] = PROJ_ELEMS/4;
    cv.s[3] = Wk;    cv.d[3] = hwk;  cv.n4[3] = WELEMS/4;
    cv.s[4] = Wv;    cv.d[4] = hwv;  cv.n4[4] = WELEMS/4;
    cv.s[5] = Wq;    cv.d[5] = hwq;  cv.n4[5] = WELEMS/4;
    cv.s[6] = Wo;    cv.d[6] = hwo;  cv.n4[6] = WELEMS/4;
    cvt7_kernel<<<dim3(512,7,1), 256>>>(cv);

    // 1: merged QKV projections (all-fp16, 3-stage cp.async, 2 blocks/SM)
    P3 p;
    p.A[0] = hkey; p.W[0] = hwk; p.b[0] = bk; p.C[0] = pk; p.s[0] = 1.0f;
    p.A[1] = hval; p.W[1] = hwv; p.b[1] = bv; p.C[1] = pv; p.s[1] = 1.0f;
    p.A[2] = hqin; p.W[2] = hwq; p.b[2] = bq; p.C[2] = pq; p.s[2] = 0.125f;
    proj3_kernel<<<dim3(8,32,3), 512, P3_SMEM>>>(p);

    // 2: QK logits = Q·K^T
    qk_fn<<<dim3(8,8,BHN), 512, QK_SMEM>>>(
        pq, pk, nullptr, plog, DHD,
        DHD, DHD, LSEQ,
        LD, LD, LL,
        1.0f, nullptr);

    // 3: fused QR + mask + softmax(no-max) + AR
    pass2_fused<<<1024, 512, P2_SMEM_BYTES>>>(pq, rel_k, rel_v, plog, mask, pctx, pinvs);

    // 4: AV: ctx = (alpha'·V + AR') * inv_s (4-stage cp.async)
    av_fn<<<dim3(1,8,BHN), 512, AV_SMEM>>>(
        plog, pv, nullptr, pctx, LSEQ,
        LSEQ, DHD, DHD,
        LL, LD, LD,
        1.0f, pinvs);

    // 5: out = ctx @ Wo^T + bo (fp16 Wo, 3-stage cp.async, fp32 output)
    out_fn<<<dim3(8,32,1), 512, OUT_SMEM>>>(
        pctx, hwo, bo, out, DMODEL,
        0, DMODEL, DMODEL,
        0, 0, 0,
        1.0f, nullptr);
}